// round 14
// baseline (speedup 1.0000x reference)
#include <cuda_runtime.h>
#include <cuda_bf16.h>
#include <cuda_fp16.h>
#include <cstdint>

#define N_NODES 50000
#define N_EDGES 800000
#define N_GRAPHS 1024
#define NBLK 391                 // ceil(50000/128)
#define TILE_E 5120              // elems per 10240B tile (128 rows x 40)
#define FEAT_E ((size_t)NBLK * 16 * TILE_E)

// ---------------- device-global scratch (allocation-free rule) -------------
__device__ float g_z[(size_t)N_NODES * 128];      // FC output
__device__ __half g_h16[(size_t)N_NODES * 512];   // fp16 inter-layer features
__device__ __half g_x16[(size_t)N_NODES * 78];    // fp16 copy of x
// tiled bf16 feature buffers: [block][chunk][128x40]
__device__ __nv_bfloat16 g_agg_hi[FEAT_E];
__device__ __nv_bfloat16 g_agg_lo[FEAT_E];
__device__ __nv_bfloat16 g_bufA_hi[FEAT_E];
__device__ __nv_bfloat16 g_bufA_lo[FEAT_E];
__device__ __nv_bfloat16 g_bufB_hi[FEAT_E];
__device__ __nv_bfloat16 g_bufB_lo[FEAT_E];
// tiled weights (bf16 hi/lo), offsets in elems:
// W1r:0 W1o:30720 W2r:61440 W2o:225280 W3r:389120 W3o:716800 Wfc:1044480
__device__ __nv_bfloat16 g_wt_hi[1126400];
__device__ __nv_bfloat16 g_wt_lo[1126400];
// CSR
__device__ int g_cnt[N_NODES];
__device__ int g_off[N_NODES + 1];
__device__ int g_cur[N_NODES];
__device__ int g_srcs[N_EDGES];
__device__ int g_bsum[64];

// ---------------------------------------------------------------------------
__global__ void zero_kernel(float4* __restrict__ p, int n4) {
    int i = blockIdx.x * blockDim.x + threadIdx.x;
    int stride = gridDim.x * blockDim.x;
    float4 z = make_float4(0.f, 0.f, 0.f, 0.f);
    for (; i < n4; i += stride) p[i] = z;
}

__global__ void zero_int(int* __restrict__ p, int n) {
    int i = blockIdx.x * blockDim.x + threadIdx.x;
    if (i < n) p[i] = 0;
}

// ---------------------------------------------------------------------------
// Fused weight prep -> tiled [colblock][chunk][128x40] bf16 hi/lo
// ---------------------------------------------------------------------------
struct PrepArgs {
    const float* W[7];
    int K[7];
    int M[7];
    int Kpad[7];
    int off[7];
};

__global__ void prep_all(PrepArgs a,
                         __nv_bfloat16* __restrict__ hi,
                         __nv_bfloat16* __restrict__ lo) {
    int seg = blockIdx.y;
    int idx = blockIdx.x * blockDim.x + threadIdx.x;
    int Kpad = a.Kpad[seg];
    if (idx >= a.M[seg] * Kpad) return;
    int n = idx / Kpad, k = idx % Kpad;
    int K = a.K[seg];
    int nch = Kpad >> 5;
    float v = (k < K) ? a.W[seg][(size_t)k * a.M[seg] + n] : 0.f;
    __nv_bfloat16 h = __float2bfloat16(v);
    size_t o = (size_t)a.off[seg]
             + ((size_t)(n >> 7) * nch + (k >> 5)) * TILE_E
             + (n & 127) * 40 + (k & 31);
    hi[o] = h;
    lo[o] = __float2bfloat16(v - __bfloat162float(h));
}

// x [N,78] fp32 -> tiled hi/lo (Kpad 96) + fp16 row-major copy
__global__ void prep_x(const float* __restrict__ x,
                       __nv_bfloat16* __restrict__ hi,
                       __nv_bfloat16* __restrict__ lo,
                       __half* __restrict__ x16) {
    int idx = blockIdx.x * blockDim.x + threadIdx.x;
    if (idx >= N_NODES * 96) return;
    int n = idx / 96, k = idx % 96;
    float v = (k < 78) ? x[(size_t)n * 78 + k] : 0.f;
    __nv_bfloat16 h = __float2bfloat16(v);
    size_t o = ((size_t)(n >> 7) * 3 + (k >> 5)) * TILE_E
             + (n & 127) * 40 + (k & 31);
    hi[o] = h;
    lo[o] = __float2bfloat16(v - __bfloat162float(h));
    if (k < 78) x16[(size_t)n * 78 + k] = __float2half(v);
}

// ---------------------------------------------------------------------------
// CSR build
// ---------------------------------------------------------------------------
__global__ void hist_kernel(const int* __restrict__ ei) {
    int e = blockIdx.x * blockDim.x + threadIdx.x;
    if (e < N_EDGES) atomicAdd(&g_cnt[ei[N_EDGES + e]], 1);
}

__global__ void scan1(void) {
    __shared__ int sm[1024];
    int tid = threadIdx.x;
    int i = blockIdx.x * 1024 + tid;
    int v = (i < N_NODES) ? g_cnt[i] : 0;
    sm[tid] = v;
    __syncthreads();
    for (int o = 1; o < 1024; o <<= 1) {
        int t = (tid >= o) ? sm[tid - o] : 0;
        __syncthreads();
        sm[tid] += t;
        __syncthreads();
    }
    if (i < N_NODES) g_off[i] = sm[tid] - v;
    if (tid == 1023) g_bsum[blockIdx.x] = sm[1023];
}

__global__ void scan3(void) {
    int i = blockIdx.x * blockDim.x + threadIdx.x;
    if (i < N_NODES) {
        int blk = i >> 10;
        int run = 0;
        for (int b = 0; b < blk; ++b) run += g_bsum[b];
        int o = g_off[i] + run;
        g_off[i] = o;
        g_cur[i] = o;
    }
    if (i == 0) g_off[N_NODES] = N_EDGES;
}

__global__ void fill_kernel(const int* __restrict__ ei) {
    int e = blockIdx.x * blockDim.x + threadIdx.x;
    if (e >= N_EDGES) return;
    int s = ei[e], t = ei[N_EDGES + e];
    int pos = atomicAdd(&g_cur[t], 1);
    g_srcs[pos] = s;
}

// ---------------------------------------------------------------------------
// CSR gather from fp16 x copy (layer 1) -> tiled bf16 hi/lo.  Warp per node.
// ---------------------------------------------------------------------------
__global__ void gather78(const __half* __restrict__ x,
                         __nv_bfloat16* __restrict__ ahi,
                         __nv_bfloat16* __restrict__ alo) {
    int n = (blockIdx.x * blockDim.x + threadIdx.x) >> 5;
    int lane = threadIdx.x & 31;
    if (n >= N_NODES) return;
    int jb = g_off[n], je = g_off[n + 1];
    float a0 = 0.f, a1 = 0.f, a2 = 0.f;
    for (int j = jb; j < je; ++j) {
        const __half* xr = x + (size_t)g_srcs[j] * 78;
        a0 += __half2float(__ldg(xr + lane));
        a1 += __half2float(__ldg(xr + lane + 32));
        if (lane < 14) a2 += __half2float(__ldg(xr + lane + 64));
    }
    float vals[3] = {a0, a1, (lane < 14) ? a2 : 0.f};
    size_t tbase = (size_t)(n >> 7) * 3;
    int rr = (n & 127) * 40 + lane;
    #pragma unroll
    for (int i = 0; i < 3; ++i) {
        size_t o = (tbase + i) * TILE_E + rr;
        __nv_bfloat16 h = __float2bfloat16(vals[i]);
        ahi[o] = h;
        alo[o] = __float2bfloat16(vals[i] - __bfloat162float(h));
    }
}

// CSR gather from fp16 features (layers 2,3): half the bytes of fp32.
__global__ void gather_h16(const __half* __restrict__ x, int d,
                           __nv_bfloat16* __restrict__ ahi,
                           __nv_bfloat16* __restrict__ alo) {
    int n = (blockIdx.x * blockDim.x + threadIdx.x) >> 5;
    int lane = threadIdx.x & 31;
    if (n >= N_NODES) return;
    int jb = g_off[n], je = g_off[n + 1];
    int ng = d >> 8;                    // 256-elem groups (1 or 2)
    float acc[16];
    #pragma unroll
    for (int i = 0; i < 16; ++i) acc[i] = 0.f;
    for (int j = jb; j < je; ++j) {
        const __half* xr = x + (size_t)g_srcs[j] * d;
        #pragma unroll 2
        for (int g = 0; g < ng; ++g) {
            uint4 v = __ldg((const uint4*)(xr + g * 256) + lane);
            const __half2* hp = (const __half2*)&v;
            #pragma unroll
            for (int p = 0; p < 4; ++p) {
                float2 f = __half22float2(hp[p]);
                acc[g * 8 + p * 2]     += f.x;
                acc[g * 8 + p * 2 + 1] += f.y;
            }
        }
    }
    size_t tb = (size_t)(n >> 7) * (d >> 5);
    int rbase = (n & 127) * 40;
    for (int g = 0; g < ng; ++g) {
        int c0 = g * 256 + lane * 8;
        int ch = c0 >> 5;
        int co = c0 & 31;
        #pragma unroll
        for (int hf = 0; hf < 2; ++hf) {
            float a0 = acc[g * 8 + hf * 4 + 0];
            float a1 = acc[g * 8 + hf * 4 + 1];
            float a2 = acc[g * 8 + hf * 4 + 2];
            float a3 = acc[g * 8 + hf * 4 + 3];
            __nv_bfloat162 h01 = __floats2bfloat162_rn(a0, a1);
            __nv_bfloat162 h23 = __floats2bfloat162_rn(a2, a3);
            __nv_bfloat162 l01 = __floats2bfloat162_rn(
                a0 - __bfloat162float(h01.x), a1 - __bfloat162float(h01.y));
            __nv_bfloat162 l23 = __floats2bfloat162_rn(
                a2 - __bfloat162float(h23.x), a3 - __bfloat162float(h23.y));
            size_t o = (tb + ch) * TILE_E + rbase + co + hf * 4;
            *(uint2*)(ahi + o) = make_uint2(*(unsigned*)&h01, *(unsigned*)&h23);
            *(uint2*)(alo + o) = make_uint2(*(unsigned*)&l01, *(unsigned*)&l23);
        }
    }
}

// ---------------------------------------------------------------------------
// mma / ldmatrix / bulk-copy helpers
// ---------------------------------------------------------------------------
__device__ __forceinline__ void mma_bf16(float* c, const unsigned* a,
                                         unsigned b0, unsigned b1) {
    asm volatile(
        "mma.sync.aligned.m16n8k16.row.col.f32.bf16.bf16.f32 "
        "{%0,%1,%2,%3}, {%4,%5,%6,%7}, {%8,%9}, {%0,%1,%2,%3};"
        : "+f"(c[0]), "+f"(c[1]), "+f"(c[2]), "+f"(c[3])
        : "r"(a[0]), "r"(a[1]), "r"(a[2]), "r"(a[3]), "r"(b0), "r"(b1));
}

__device__ __forceinline__ void ldm_x4(unsigned* r, uint32_t addr) {
    asm volatile(
        "ldmatrix.sync.aligned.m8n8.x4.shared.b16 {%0,%1,%2,%3}, [%4];"
        : "=r"(r[0]), "=r"(r[1]), "=r"(r[2]), "=r"(r[3]) : "r"(addr));
}

__device__ __forceinline__ void ldm_x2(unsigned* r, uint32_t addr) {
    asm volatile(
        "ldmatrix.sync.aligned.m8n8.x2.shared.b16 {%0,%1}, [%2];"
        : "=r"(r[0]), "=r"(r[1]) : "r"(addr));
}

__device__ __forceinline__ void bulkcp(uint32_t dst, const void* src,
                                       uint32_t mbar) {
    asm volatile(
        "cp.async.bulk.shared::cluster.global.mbarrier::complete_tx::bytes "
        "[%0], [%1], %2, [%3];"
        :: "r"(dst), "l"(src), "r"(10240u), "r"(mbar) : "memory");
}

__device__ __forceinline__ void mbar_wait(uint32_t addr, uint32_t phase) {
    asm volatile(
        "{\n\t.reg .pred p;\n\t"
        "WL%=:\n\t"
        "mbarrier.try_wait.parity.acquire.cta.shared::cta.b64 p, [%0], %1, 0x989680;\n\t"
        "@p bra WD%=;\n\t"
        "bra WL%=;\n\t"
        "WD%=:\n\t}"
        :: "r"(addr), "r"(phase) : "memory");
}

// ---------------------------------------------------------------------------
// Dual/single GEMM (bf16 hi/lo 3-term split), cp.async.bulk double-buffered.
// Warp grid 2x4 (64x32 per warp): 32 LDSM / 96 MMA per iter per warp
// (vs 40 LDSM at 4x2) -- cuts LDSM issue pressure 20%.
// ---------------------------------------------------------------------------
#define TILE_B 10240
#define STAGE_B 40960

__global__ __launch_bounds__(256, 2)
void dual_gemm_bf16(const __nv_bfloat16* __restrict__ A1h,
                    const __nv_bfloat16* __restrict__ A1l,
                    const __nv_bfloat16* __restrict__ A2h,
                    const __nv_bfloat16* __restrict__ A2l,
                    const __nv_bfloat16* __restrict__ B1h,
                    const __nv_bfloat16* __restrict__ B1l,
                    const __nv_bfloat16* __restrict__ B2h,
                    const __nv_bfloat16* __restrict__ B2l,
                    const float* __restrict__ bias, float* __restrict__ C,
                    __half* __restrict__ C16,
                    __nv_bfloat16* __restrict__ Chi,
                    __nv_bfloat16* __restrict__ Clo,
                    int N, int Kpad, int M, int do_relu) {
    extern __shared__ __align__(16) char dynsmem[];
    __shared__ __align__(8) uint64_t s_mbar[2];
    uint32_t ubase = (uint32_t)__cvta_generic_to_shared(dynsmem);
    uint32_t mbase = (uint32_t)__cvta_generic_to_shared(s_mbar);

    int tid = threadIdx.x;
    int lane = tid & 31, wid = tid >> 5;
    int wr = wid & 1, wc = wid >> 1;        // 2x4 warp grid
    int m0w = wr * 64, n0w = wc * 32;       // 64x32 warp tile
    int gid = lane >> 2, tig = lane & 3;

    int rowBase = blockIdx.y * 128;
    int colBase = blockIdx.x * 128;

    int a_row = (lane & 7) + ((lane >> 3) & 1) * 8;
    int a_koff = (lane >> 4) * 16;
    int b_row = lane & 7;
    int b_koff = ((lane >> 3) & 1) * 16;

    if (tid == 0) {
        asm volatile("mbarrier.init.shared.b64 [%0], 1;" :: "r"(mbase) : "memory");
        asm volatile("mbarrier.init.shared.b64 [%0], 1;" :: "r"(mbase + 8) : "memory");
    }
    __syncthreads();

    float acc[4][4][4];
    #pragma unroll
    for (int mt = 0; mt < 4; mt++)
        #pragma unroll
        for (int nt = 0; nt < 4; nt++)
            #pragma unroll
            for (int i = 0; i < 4; i++) acc[mt][nt][i] = 0.f;

    const int nch = Kpad >> 5;
    const int npass = (A2h != nullptr) ? 2 : 1;
    const int T = npass * nch;

    auto issue = [&](int it, int st) {
        if (tid == 0) {
            int pass = (it >= nch) ? 1 : 0;
            int ch = it - pass * nch;
            const __nv_bfloat16* AH = pass ? A2h : A1h;
            const __nv_bfloat16* AL = pass ? A2l : A1l;
            const __nv_bfloat16* BH = pass ? B2h : B1h;
            const __nv_bfloat16* BL = pass ? B2l : B1l;
            uint32_t mb = mbase + st * 8;
            asm volatile("mbarrier.arrive.expect_tx.shared.b64 _, [%0], %1;"
                         :: "r"(mb), "r"(40960u) : "memory");
            uint32_t sb = ubase + st * STAGE_B;
            size_t at = ((size_t)blockIdx.y * nch + ch) * TILE_E;
            size_t bt = ((size_t)blockIdx.x * nch + ch) * TILE_E;
            bulkcp(sb,              AH + at, mb);
            bulkcp(sb + TILE_B,     AL + at, mb);
            bulkcp(sb + 2 * TILE_B, BH + bt, mb);
            bulkcp(sb + 3 * TILE_B, BL + bt, mb);
        }
    };

    int ph0 = 0, ph1 = 0;
    issue(0, 0);

    #pragma unroll 1
    for (int it = 0; it < T; ++it) {
        if (it + 1 < T) issue(it + 1, (it + 1) & 1);
        int st = it & 1;
        mbar_wait(mbase + st * 8, st ? ph1 : ph0);
        if (st) ph1 ^= 1; else ph0 ^= 1;

        uint32_t sb = ubase + st * STAGE_B;
        uint32_t uAh = sb, uAl = sb + TILE_B;
        uint32_t uBh = sb + 2 * TILE_B, uBl = sb + 3 * TILE_B;

        #pragma unroll
        for (int ks = 0; ks < 2; ++ks) {
            int kb = ks * 32;
            unsigned ah[4][4], al[4][4];
            #pragma unroll
            for (int mt = 0; mt < 4; mt++) {
                uint32_t ao = (uint32_t)((m0w + mt * 16 + a_row) * 80
                                         + kb + a_koff);
                ldm_x4(ah[mt], uAh + ao);
                ldm_x4(al[mt], uAl + ao);
            }
            #pragma unroll
            for (int nt = 0; nt < 4; nt++) {
                uint32_t bo = (uint32_t)((n0w + nt * 8 + b_row) * 80
                                         + kb + b_koff);
                unsigned bh[2], bl[2];
                ldm_x2(bh, uBh + bo);
                ldm_x2(bl, uBl + bo);
                #pragma unroll
                for (int mt = 0; mt < 4; mt++) {
                    mma_bf16(acc[mt][nt], ah[mt], bh[0], bh[1]);
                    mma_bf16(acc[mt][nt], al[mt], bh[0], bh[1]);
                    mma_bf16(acc[mt][nt], ah[mt], bl[0], bl[1]);
                }
            }
        }
        __syncthreads();   // all reads done before next bulk overwrites stage
    }

    // ---- Epilogue ----
    const int nchC = M >> 5;
    #pragma unroll
    for (int mt = 0; mt < 4; mt++) {
        #pragma unroll
        for (int nt = 0; nt < 4; nt++) {
            int r = rowBase + m0w + mt * 16 + gid;
            int c = colBase + n0w + nt * 8 + tig * 2;
            float b0v = bias[c], b1v = bias[c + 1];
            #pragma unroll
            for (int half = 0; half < 2; ++half) {
                int rr = r + half * 8;
                if (rr >= N) continue;
                float v0 = acc[mt][nt][2 * half + 0] + b0v;
                float v1 = acc[mt][nt][2 * half + 1] + b1v;
                if (do_relu) {
                    v0 = v0 > 0.f ? v0 : 0.f;
                    v1 = v1 > 0.f ? v1 : 0.f;
                }
                if (C) {
                    size_t o = (size_t)rr * M + c;
                    C[o] = v0;
                    C[o + 1] = v1;
                }
                if (C16) {
                    size_t o = (size_t)rr * M + c;
                    *(__half2*)(C16 + o) = __floats2half2_rn(v0, v1);
                }
                if (Chi) {
                    size_t o = ((size_t)blockIdx.y * nchC + (c >> 5)) * TILE_E
                             + (rr & 127) * 40 + (c & 31);
                    __nv_bfloat162 hh = __floats2bfloat162_rn(v0, v1);
                    __nv_bfloat162 ll = __floats2bfloat162_rn(
                        v0 - __bfloat162float(hh.x), v1 - __bfloat162float(hh.y));
                    *(unsigned*)(Chi + o) = *(unsigned*)&hh;
                    *(unsigned*)(Clo + o) = *(unsigned*)&ll;
                }
            }
        }
    }
}

// ---------------------------------------------------------------------------
// LayerNorm(128) + ReLU + pooling.  Warp per row group; no block syncs.
// ---------------------------------------------------------------------------
#define LNW 32

__global__ __launch_bounds__(256)
void ln_pool(const float* __restrict__ z, const float* __restrict__ lng,
             const float* __restrict__ lnb, const int* __restrict__ batch,
             float* __restrict__ xa, float* __restrict__ pooled, int N) {
    int warp = (blockIdx.x * blockDim.x + threadIdx.x) >> 5;
    int lane = threadIdx.x & 31;
    int r0 = warp * LNW;
    if (r0 >= N) return;
    int r1 = min(r0 + LNW, N);

    float4 g = ((const float4*)lng)[lane];
    float4 b = ((const float4*)lnb)[lane];

    float4 pacc = make_float4(0.f, 0.f, 0.f, 0.f);
    int curg = -1;
    for (int r = r0; r < r1; ++r) {
        float4 v = ((const float4*)(z + (size_t)r * 128))[lane];
        float s = v.x + v.y + v.z + v.w;
        float s2 = v.x * v.x + v.y * v.y + v.z * v.z + v.w * v.w;
        #pragma unroll
        for (int o = 16; o > 0; o >>= 1) {
            s  += __shfl_xor_sync(0xffffffffu, s, o);
            s2 += __shfl_xor_sync(0xffffffffu, s2, o);
        }
        float mu = s * (1.f / 128.f);
        float var = s2 * (1.f / 128.f) - mu * mu;
        float inv = rsqrtf(var + 1e-5f);
        float4 zz;
        zz.x = fmaxf((v.x - mu) * inv * g.x + b.x, 0.f);
        zz.y = fmaxf((v.y - mu) * inv * g.y + b.y, 0.f);
        zz.z = fmaxf((v.z - mu) * inv * g.z + b.z, 0.f);
        zz.w = fmaxf((v.w - mu) * inv * g.w + b.w, 0.f);
        ((float4*)(xa + (size_t)r * 128))[lane] = zz;

        int gb = batch[r];
        if (gb != curg) {
            if (curg >= 0) {
                float* pd = pooled + (size_t)curg * 128 + lane * 4;
                atomicAdd(pd + 0, pacc.x);
                atomicAdd(pd + 1, pacc.y);
                atomicAdd(pd + 2, pacc.z);
                atomicAdd(pd + 3, pacc.w);
            }
            curg = gb;
            pacc = make_float4(0.f, 0.f, 0.f, 0.f);
        }
        pacc.x += zz.x; pacc.y += zz.y; pacc.z += zz.z; pacc.w += zz.w;
    }
    if (curg >= 0) {
        float* pd = pooled + (size_t)curg * 128 + lane * 4;
        atomicAdd(pd + 0, pacc.x);
        atomicAdd(pd + 1, pacc.y);
        atomicAdd(pd + 2, pacc.z);
        atomicAdd(pd + 3, pacc.w);
    }
}

// ---------------------------------------------------------------------------
// Launch (prep chain + pooled zero overlapped on a second stream)
// ---------------------------------------------------------------------------
extern "C" void kernel_launch(void* const* d_in, const int* in_sizes, int n_in,
                              void* d_out, int out_size) {
    const float* x     = (const float*)d_in[0];
    const int*   ei    = (const int*)d_in[1];
    const int*   batch = (const int*)d_in[2];
    const float* W1r = (const float*)d_in[3];
    const float* b1  = (const float*)d_in[4];
    const float* W1o = (const float*)d_in[5];
    const float* W2r = (const float*)d_in[6];
    const float* b2  = (const float*)d_in[7];
    const float* W2o = (const float*)d_in[8];
    const float* W3r = (const float*)d_in[9];
    const float* b3  = (const float*)d_in[10];
    const float* W3o = (const float*)d_in[11];
    const float* Wfc = (const float*)d_in[12];
    const float* bfc = (const float*)d_in[13];
    const float* lng = (const float*)d_in[14];
    const float* lnb = (const float*)d_in[15];

    float* out = (float*)d_out;
    float* x_atom = out;
    float* pooled = out + (size_t)N_NODES * 128;

    float* zbuf;
    __half *h16, *x16;
    __nv_bfloat16 *aggh, *aggl, *bAh, *bAl, *bBh, *bBl, *wth, *wtl;
    cudaGetSymbolAddress((void**)&zbuf, g_z);
    cudaGetSymbolAddress((void**)&h16, g_h16);
    cudaGetSymbolAddress((void**)&x16, g_x16);
    cudaGetSymbolAddress((void**)&aggh, g_agg_hi);
    cudaGetSymbolAddress((void**)&aggl, g_agg_lo);
    cudaGetSymbolAddress((void**)&bAh, g_bufA_hi);
    cudaGetSymbolAddress((void**)&bAl, g_bufA_lo);
    cudaGetSymbolAddress((void**)&bBh, g_bufB_hi);
    cudaGetSymbolAddress((void**)&bBl, g_bufB_lo);
    cudaGetSymbolAddress((void**)&wth, g_wt_hi);
    cudaGetSymbolAddress((void**)&wtl, g_wt_lo);

    cudaFuncSetAttribute(dual_gemm_bf16,
                         cudaFuncAttributeMaxDynamicSharedMemorySize, 81920);

    static cudaStream_t sB = nullptr;
    static cudaEvent_t evFork = nullptr, evJoin = nullptr;
    if (sB == nullptr) {
        cudaStreamCreateWithFlags(&sB, cudaStreamNonBlocking);
        cudaEventCreateWithFlags(&evFork, cudaEventDisableTiming);
        cudaEventCreateWithFlags(&evJoin, cudaEventDisableTiming);
    }

    const int gridY = NBLK;
    const int gatherBlocks = (N_NODES * 32 + 255) / 256;

    // ---- fork: weight/x prep + pooled zero on stream sB ----
    cudaEventRecord(evFork, 0);
    cudaStreamWaitEvent(sB, evFork, 0);
    {
        PrepArgs pa;
        pa.W[0] = W1r; pa.K[0] = 78;  pa.M[0] = 256; pa.Kpad[0] = 96;  pa.off[0] = 0;
        pa.W[1] = W1o; pa.K[1] = 78;  pa.M[1] = 256; pa.Kpad[1] = 96;  pa.off[1] = 30720;
        pa.W[2] = W2r; pa.K[2] = 256; pa.M[2] = 512; pa.Kpad[2] = 256; pa.off[2] = 61440;
        pa.W[3] = W2o; pa.K[3] = 256; pa.M[3] = 512; pa.Kpad[3] = 256; pa.off[3] = 225280;
        pa.W[4] = W3r; pa.K[4] = 512; pa.M[4] = 512; pa.Kpad[4] = 512; pa.off[4] = 389120;
        pa.W[5] = W3o; pa.K[5] = 512; pa.M[5] = 512; pa.Kpad[5] = 512; pa.off[5] = 716800;
        pa.W[6] = Wfc; pa.K[6] = 512; pa.M[6] = 128; pa.Kpad[6] = 512; pa.off[6] = 1044480;
        dim3 grid((512 * 512 + 255) / 256, 7);
        prep_all<<<grid, 256, 0, sB>>>(pa, wth, wtl);
    }
    prep_x<<<(N_NODES * 96 + 255) / 256, 256, 0, sB>>>(x, bAh, bAl, x16);
    zero_kernel<<<128, 256, 0, sB>>>((float4*)pooled, N_GRAPHS * 128 / 4);
    cudaEventRecord(evJoin, sB);

    // main stream: CSR build
    {
        int* pcnt; cudaGetSymbolAddress((void**)&pcnt, g_cnt);
        zero_int<<<(N_NODES + 255) / 256, 256>>>(pcnt, N_NODES);
    }
    hist_kernel<<<(N_EDGES + 255) / 256, 256>>>(ei);
    scan1<<<(N_NODES + 1023) / 1024, 1024>>>();
    scan3<<<(N_NODES + 255) / 256, 256>>>();
    fill_kernel<<<(N_EDGES + 255) / 256, 256>>>(ei);

    // join before layer-1 gather (needs x16 from prep_x)
    cudaStreamWaitEvent(0, evJoin, 0);
    gather78<<<gatherBlocks, 256>>>(x16, aggh, aggl);

    // ---- Layer 1: 78 -> 256 (out: fp16 h + tiled bf16 hi/lo) ----
    {
        dim3 grid(2, gridY);
        dual_gemm_bf16<<<grid, 256, 81920>>>(aggh, aggl, bAh, bAl,
                                             wth + 0, wtl + 0,
                                             wth + 30720, wtl + 30720,
                                             b1, (float*)nullptr, h16, bBh, bBl,
                                             N_NODES, 96, 256, 1);
    }

    // ---- Layer 2: 256 -> 512 ----
    gather_h16<<<gatherBlocks, 256>>>(h16, 256, aggh, aggl);
    {
        dim3 grid(4, gridY);
        dual_gemm_bf16<<<grid, 256, 81920>>>(aggh, aggl, bBh, bBl,
                                             wth + 61440, wtl + 61440,
                                             wth + 225280, wtl + 225280,
                                             b2, (float*)nullptr, h16, bAh, bAl,
                                             N_NODES, 256, 512, 1);
    }

    // ---- Layer 3: 512 -> 512 ----
    gather_h16<<<gatherBlocks, 256>>>(h16, 512, aggh, aggl);
    {
        dim3 grid(4, gridY);
        dual_gemm_bf16<<<grid, 256, 81920>>>(aggh, aggl, bAh, bAl,
                                             wth + 389120, wtl + 389120,
                                             wth + 716800, wtl + 716800,
                                             b3, (float*)nullptr, (__half*)nullptr,
                                             bBh, bBl,
                                             N_NODES, 512, 512, 1);
    }

    // ---- FC 512->128 via GEMM (no relu), then LN + ReLU + pool ----
    {
        dim3 grid(1, gridY);
        dual_gemm_bf16<<<grid, 256, 81920>>>(bBh, bBl,
                                             (__nv_bfloat16*)nullptr,
                                             (__nv_bfloat16*)nullptr,
                                             wth + 1044480, wtl + 1044480,
                                             (__nv_bfloat16*)nullptr,
                                             (__nv_bfloat16*)nullptr,
                                             bfc, zbuf, (__half*)nullptr,
                                             (__nv_bfloat16*)nullptr,
                                             (__nv_bfloat16*)nullptr,
                                             N_NODES, 512, 128, 0);
    }
    {
        int warps = (N_NODES + LNW - 1) / LNW;
        ln_pool<<<(warps * 32 + 255) / 256, 256>>>(
            zbuf, lng, lnb, batch, x_atom, pooled, N_NODES);
    }
}

// round 15
// speedup vs baseline: 1.0816x; 1.0816x over previous
#include <cuda_runtime.h>
#include <cuda_bf16.h>
#include <cuda_fp16.h>
#include <cstdint>

#define N_NODES 50000
#define N_EDGES 800000
#define N_GRAPHS 1024
#define NBLK 391                 // ceil(50000/128)
#define TILE_E 5120              // elems per 10240B tile (128 rows x 40)
#define FEAT_E ((size_t)NBLK * 16 * TILE_E)

// ---------------- device-global scratch (allocation-free rule) -------------
__device__ float g_z[(size_t)N_NODES * 128];      // FC output
__device__ __half g_h16[(size_t)N_NODES * 512];   // fp16 inter-layer features
__device__ __half g_x16[(size_t)N_NODES * 78];    // fp16 copy of x
// tiled bf16 feature buffers: [block][chunk][128x40]
__device__ __nv_bfloat16 g_agg_hi[FEAT_E];
__device__ __nv_bfloat16 g_agg_lo[FEAT_E];
__device__ __nv_bfloat16 g_bufA_hi[FEAT_E];
__device__ __nv_bfloat16 g_bufA_lo[FEAT_E];
__device__ __nv_bfloat16 g_bufB_hi[FEAT_E];
__device__ __nv_bfloat16 g_bufB_lo[FEAT_E];
// tiled weights (bf16 hi/lo), offsets in elems:
// W1r:0 W1o:30720 W2r:61440 W2o:225280 W3r:389120 W3o:716800 Wfc:1044480
__device__ __nv_bfloat16 g_wt_hi[1126400];
__device__ __nv_bfloat16 g_wt_lo[1126400];
// CSR
__device__ int g_cnt[N_NODES];
__device__ int g_off[N_NODES + 1];
__device__ int g_cur[N_NODES];
__device__ int g_srcs[N_EDGES];
__device__ int g_bsum[64];

// ---------------------------------------------------------------------------
__global__ void zero_kernel(float4* __restrict__ p, int n4) {
    int i = blockIdx.x * blockDim.x + threadIdx.x;
    int stride = gridDim.x * blockDim.x;
    float4 z = make_float4(0.f, 0.f, 0.f, 0.f);
    for (; i < n4; i += stride) p[i] = z;
}

__global__ void zero_int(int* __restrict__ p, int n) {
    int i = blockIdx.x * blockDim.x + threadIdx.x;
    if (i < n) p[i] = 0;
}

// ---------------------------------------------------------------------------
// Fused weight prep -> tiled [colblock][chunk][128x40] bf16 hi/lo
// ---------------------------------------------------------------------------
struct PrepArgs {
    const float* W[7];
    int K[7];
    int M[7];
    int Kpad[7];
    int off[7];
};

__global__ void prep_all(PrepArgs a,
                         __nv_bfloat16* __restrict__ hi,
                         __nv_bfloat16* __restrict__ lo) {
    int seg = blockIdx.y;
    int idx = blockIdx.x * blockDim.x + threadIdx.x;
    int Kpad = a.Kpad[seg];
    if (idx >= a.M[seg] * Kpad) return;
    int n = idx / Kpad, k = idx % Kpad;
    int K = a.K[seg];
    int nch = Kpad >> 5;
    float v = (k < K) ? a.W[seg][(size_t)k * a.M[seg] + n] : 0.f;
    __nv_bfloat16 h = __float2bfloat16(v);
    size_t o = (size_t)a.off[seg]
             + ((size_t)(n >> 7) * nch + (k >> 5)) * TILE_E
             + (n & 127) * 40 + (k & 31);
    hi[o] = h;
    lo[o] = __float2bfloat16(v - __bfloat162float(h));
}

// x [N,78] fp32 -> tiled hi/lo (Kpad 96) + fp16 row-major copy
__global__ void prep_x(const float* __restrict__ x,
                       __nv_bfloat16* __restrict__ hi,
                       __nv_bfloat16* __restrict__ lo,
                       __half* __restrict__ x16) {
    int idx = blockIdx.x * blockDim.x + threadIdx.x;
    if (idx >= N_NODES * 96) return;
    int n = idx / 96, k = idx % 96;
    float v = (k < 78) ? x[(size_t)n * 78 + k] : 0.f;
    __nv_bfloat16 h = __float2bfloat16(v);
    size_t o = ((size_t)(n >> 7) * 3 + (k >> 5)) * TILE_E
             + (n & 127) * 40 + (k & 31);
    hi[o] = h;
    lo[o] = __float2bfloat16(v - __bfloat162float(h));
    if (k < 78) x16[(size_t)n * 78 + k] = __float2half(v);
}

// ---------------------------------------------------------------------------
// CSR build
// ---------------------------------------------------------------------------
__global__ void hist_kernel(const int* __restrict__ ei) {
    int e = blockIdx.x * blockDim.x + threadIdx.x;
    if (e < N_EDGES) atomicAdd(&g_cnt[ei[N_EDGES + e]], 1);
}

__global__ void scan1(void) {
    __shared__ int sm[1024];
    int tid = threadIdx.x;
    int i = blockIdx.x * 1024 + tid;
    int v = (i < N_NODES) ? g_cnt[i] : 0;
    sm[tid] = v;
    __syncthreads();
    for (int o = 1; o < 1024; o <<= 1) {
        int t = (tid >= o) ? sm[tid - o] : 0;
        __syncthreads();
        sm[tid] += t;
        __syncthreads();
    }
    if (i < N_NODES) g_off[i] = sm[tid] - v;
    if (tid == 1023) g_bsum[blockIdx.x] = sm[1023];
}

__global__ void scan3(void) {
    int i = blockIdx.x * blockDim.x + threadIdx.x;
    if (i < N_NODES) {
        int blk = i >> 10;
        int run = 0;
        for (int b = 0; b < blk; ++b) run += g_bsum[b];
        int o = g_off[i] + run;
        g_off[i] = o;
        g_cur[i] = o;
    }
    if (i == 0) g_off[N_NODES] = N_EDGES;
}

__global__ void fill_kernel(const int* __restrict__ ei) {
    int e = blockIdx.x * blockDim.x + threadIdx.x;
    if (e >= N_EDGES) return;
    int s = ei[e], t = ei[N_EDGES + e];
    int pos = atomicAdd(&g_cur[t], 1);
    g_srcs[pos] = s;
}

// ---------------------------------------------------------------------------
// CSR gather from fp16 x copy (layer 1) -> tiled bf16 hi/lo.  Warp per node.
// ---------------------------------------------------------------------------
__global__ void gather78(const __half* __restrict__ x,
                         __nv_bfloat16* __restrict__ ahi,
                         __nv_bfloat16* __restrict__ alo) {
    int n = (blockIdx.x * blockDim.x + threadIdx.x) >> 5;
    int lane = threadIdx.x & 31;
    if (n >= N_NODES) return;
    int jb = g_off[n], je = g_off[n + 1];
    float a0 = 0.f, a1 = 0.f, a2 = 0.f;
    for (int j = jb; j < je; ++j) {
        const __half* xr = x + (size_t)g_srcs[j] * 78;
        a0 += __half2float(__ldg(xr + lane));
        a1 += __half2float(__ldg(xr + lane + 32));
        if (lane < 14) a2 += __half2float(__ldg(xr + lane + 64));
    }
    float vals[3] = {a0, a1, (lane < 14) ? a2 : 0.f};
    size_t tbase = (size_t)(n >> 7) * 3;
    int rr = (n & 127) * 40 + lane;
    #pragma unroll
    for (int i = 0; i < 3; ++i) {
        size_t o = (tbase + i) * TILE_E + rr;
        __nv_bfloat16 h = __float2bfloat16(vals[i]);
        ahi[o] = h;
        alo[o] = __float2bfloat16(vals[i] - __bfloat162float(h));
    }
}

// CSR gather from fp16 features (layers 2,3): half the bytes of fp32.
__global__ void gather_h16(const __half* __restrict__ x, int d,
                           __nv_bfloat16* __restrict__ ahi,
                           __nv_bfloat16* __restrict__ alo) {
    int n = (blockIdx.x * blockDim.x + threadIdx.x) >> 5;
    int lane = threadIdx.x & 31;
    if (n >= N_NODES) return;
    int jb = g_off[n], je = g_off[n + 1];
    int ng = d >> 8;                    // 256-elem groups (1 or 2)
    float acc[16];
    #pragma unroll
    for (int i = 0; i < 16; ++i) acc[i] = 0.f;
    for (int j = jb; j < je; ++j) {
        const __half* xr = x + (size_t)g_srcs[j] * d;
        #pragma unroll 2
        for (int g = 0; g < ng; ++g) {
            uint4 v = __ldg((const uint4*)(xr + g * 256) + lane);
            const __half2* hp = (const __half2*)&v;
            #pragma unroll
            for (int p = 0; p < 4; ++p) {
                float2 f = __half22float2(hp[p]);
                acc[g * 8 + p * 2]     += f.x;
                acc[g * 8 + p * 2 + 1] += f.y;
            }
        }
    }
    size_t tb = (size_t)(n >> 7) * (d >> 5);
    int rbase = (n & 127) * 40;
    for (int g = 0; g < ng; ++g) {
        int c0 = g * 256 + lane * 8;
        int ch = c0 >> 5;
        int co = c0 & 31;
        #pragma unroll
        for (int hf = 0; hf < 2; ++hf) {
            float a0 = acc[g * 8 + hf * 4 + 0];
            float a1 = acc[g * 8 + hf * 4 + 1];
            float a2 = acc[g * 8 + hf * 4 + 2];
            float a3 = acc[g * 8 + hf * 4 + 3];
            __nv_bfloat162 h01 = __floats2bfloat162_rn(a0, a1);
            __nv_bfloat162 h23 = __floats2bfloat162_rn(a2, a3);
            __nv_bfloat162 l01 = __floats2bfloat162_rn(
                a0 - __bfloat162float(h01.x), a1 - __bfloat162float(h01.y));
            __nv_bfloat162 l23 = __floats2bfloat162_rn(
                a2 - __bfloat162float(h23.x), a3 - __bfloat162float(h23.y));
            size_t o = (tb + ch) * TILE_E + rbase + co + hf * 4;
            *(uint2*)(ahi + o) = make_uint2(*(unsigned*)&h01, *(unsigned*)&h23);
            *(uint2*)(alo + o) = make_uint2(*(unsigned*)&l01, *(unsigned*)&l23);
        }
    }
}

// ---------------------------------------------------------------------------
// mma / ldmatrix / bulk-copy helpers
// ---------------------------------------------------------------------------
__device__ __forceinline__ void mma_bf16(float* c, const unsigned* a,
                                         unsigned b0, unsigned b1) {
    asm volatile(
        "mma.sync.aligned.m16n8k16.row.col.f32.bf16.bf16.f32 "
        "{%0,%1,%2,%3}, {%4,%5,%6,%7}, {%8,%9}, {%0,%1,%2,%3};"
        : "+f"(c[0]), "+f"(c[1]), "+f"(c[2]), "+f"(c[3])
        : "r"(a[0]), "r"(a[1]), "r"(a[2]), "r"(a[3]), "r"(b0), "r"(b1));
}

__device__ __forceinline__ void ldm_x4(unsigned* r, uint32_t addr) {
    asm volatile(
        "ldmatrix.sync.aligned.m8n8.x4.shared.b16 {%0,%1,%2,%3}, [%4];"
        : "=r"(r[0]), "=r"(r[1]), "=r"(r[2]), "=r"(r[3]) : "r"(addr));
}

__device__ __forceinline__ void ldm_x2(unsigned* r, uint32_t addr) {
    asm volatile(
        "ldmatrix.sync.aligned.m8n8.x2.shared.b16 {%0,%1}, [%2];"
        : "=r"(r[0]), "=r"(r[1]) : "r"(addr));
}

__device__ __forceinline__ void bulkcp(uint32_t dst, const void* src,
                                       uint32_t mbar) {
    asm volatile(
        "cp.async.bulk.shared::cluster.global.mbarrier::complete_tx::bytes "
        "[%0], [%1], %2, [%3];"
        :: "r"(dst), "l"(src), "r"(10240u), "r"(mbar) : "memory");
}

__device__ __forceinline__ void mbar_wait(uint32_t addr, uint32_t phase) {
    asm volatile(
        "{\n\t.reg .pred p;\n\t"
        "WL%=:\n\t"
        "mbarrier.try_wait.parity.acquire.cta.shared::cta.b64 p, [%0], %1, 0x989680;\n\t"
        "@p bra WD%=;\n\t"
        "bra WL%=;\n\t"
        "WD%=:\n\t}"
        :: "r"(addr), "r"(phase) : "memory");
}

// ---------------------------------------------------------------------------
// Dual/single GEMM (bf16 hi/lo 3-term split), cp.async.bulk double-buffered.
// Warp grid 4x2 (32x64 per warp) -- PROVEN shape; do not reshape (R8/R14
// regressions: x4-pairing bank-conflicts, 2x4 scoreboard serialization).
// ---------------------------------------------------------------------------
#define TILE_B 10240
#define STAGE_B 40960

__global__ __launch_bounds__(256, 2)
void dual_gemm_bf16(const __nv_bfloat16* __restrict__ A1h,
                    const __nv_bfloat16* __restrict__ A1l,
                    const __nv_bfloat16* __restrict__ A2h,
                    const __nv_bfloat16* __restrict__ A2l,
                    const __nv_bfloat16* __restrict__ B1h,
                    const __nv_bfloat16* __restrict__ B1l,
                    const __nv_bfloat16* __restrict__ B2h,
                    const __nv_bfloat16* __restrict__ B2l,
                    const float* __restrict__ bias, float* __restrict__ C,
                    __half* __restrict__ C16,
                    __nv_bfloat16* __restrict__ Chi,
                    __nv_bfloat16* __restrict__ Clo,
                    int N, int Kpad, int M, int do_relu) {
    extern __shared__ __align__(16) char dynsmem[];
    __shared__ __align__(8) uint64_t s_mbar[2];
    uint32_t ubase = (uint32_t)__cvta_generic_to_shared(dynsmem);
    uint32_t mbase = (uint32_t)__cvta_generic_to_shared(s_mbar);

    int tid = threadIdx.x;
    int lane = tid & 31, wid = tid >> 5;
    int wr = wid & 3, wc = wid >> 2;
    int m0w = wr * 32, n0w = wc * 64;
    int gid = lane >> 2, tig = lane & 3;

    int rowBase = blockIdx.y * 128;
    int colBase = blockIdx.x * 128;

    int a_row = (lane & 7) + ((lane >> 3) & 1) * 8;
    int a_koff = (lane >> 4) * 16;
    int b_row = lane & 7;
    int b_koff = ((lane >> 3) & 1) * 16;

    if (tid == 0) {
        asm volatile("mbarrier.init.shared.b64 [%0], 1;" :: "r"(mbase) : "memory");
        asm volatile("mbarrier.init.shared.b64 [%0], 1;" :: "r"(mbase + 8) : "memory");
    }
    __syncthreads();

    float acc[2][8][4];
    #pragma unroll
    for (int mt = 0; mt < 2; mt++)
        #pragma unroll
        for (int nt = 0; nt < 8; nt++)
            #pragma unroll
            for (int i = 0; i < 4; i++) acc[mt][nt][i] = 0.f;

    const int nch = Kpad >> 5;
    const int npass = (A2h != nullptr) ? 2 : 1;
    const int T = npass * nch;

    auto issue = [&](int it, int st) {
        if (tid == 0) {
            int pass = (it >= nch) ? 1 : 0;
            int ch = it - pass * nch;
            const __nv_bfloat16* AH = pass ? A2h : A1h;
            const __nv_bfloat16* AL = pass ? A2l : A1l;
            const __nv_bfloat16* BH = pass ? B2h : B1h;
            const __nv_bfloat16* BL = pass ? B2l : B1l;
            uint32_t mb = mbase + st * 8;
            asm volatile("mbarrier.arrive.expect_tx.shared.b64 _, [%0], %1;"
                         :: "r"(mb), "r"(40960u) : "memory");
            uint32_t sb = ubase + st * STAGE_B;
            size_t at = ((size_t)blockIdx.y * nch + ch) * TILE_E;
            size_t bt = ((size_t)blockIdx.x * nch + ch) * TILE_E;
            bulkcp(sb,              AH + at, mb);
            bulkcp(sb + TILE_B,     AL + at, mb);
            bulkcp(sb + 2 * TILE_B, BH + bt, mb);
            bulkcp(sb + 3 * TILE_B, BL + bt, mb);
        }
    };

    int ph0 = 0, ph1 = 0;
    issue(0, 0);

    #pragma unroll 1
    for (int it = 0; it < T; ++it) {
        if (it + 1 < T) issue(it + 1, (it + 1) & 1);
        int st = it & 1;
        mbar_wait(mbase + st * 8, st ? ph1 : ph0);
        if (st) ph1 ^= 1; else ph0 ^= 1;

        uint32_t sb = ubase + st * STAGE_B;
        uint32_t uAh = sb, uAl = sb + TILE_B;
        uint32_t uBh = sb + 2 * TILE_B, uBl = sb + 3 * TILE_B;

        #pragma unroll
        for (int ks = 0; ks < 2; ++ks) {
            int kb = ks * 32;
            unsigned ah[2][4], al[2][4];
            #pragma unroll
            for (int mt = 0; mt < 2; mt++) {
                uint32_t ao = (uint32_t)((m0w + mt * 16 + a_row) * 80
                                         + kb + a_koff);
                ldm_x4(ah[mt], uAh + ao);
                ldm_x4(al[mt], uAl + ao);
            }
            #pragma unroll
            for (int nt = 0; nt < 8; nt++) {
                uint32_t bo = (uint32_t)((n0w + nt * 8 + b_row) * 80
                                         + kb + b_koff);
                unsigned bh[2], bl[2];
                ldm_x2(bh, uBh + bo);
                ldm_x2(bl, uBl + bo);
                #pragma unroll
                for (int mt = 0; mt < 2; mt++) {
                    mma_bf16(acc[mt][nt], ah[mt], bh[0], bh[1]);
                    mma_bf16(acc[mt][nt], al[mt], bh[0], bh[1]);
                    mma_bf16(acc[mt][nt], ah[mt], bl[0], bl[1]);
                }
            }
        }
        __syncthreads();   // all reads done before next bulk overwrites stage
    }

    // ---- Epilogue ----
    const int nchC = M >> 5;
    #pragma unroll
    for (int mt = 0; mt < 2; mt++) {
        #pragma unroll
        for (int nt = 0; nt < 8; nt++) {
            int r = rowBase + m0w + mt * 16 + gid;
            int c = colBase + n0w + nt * 8 + tig * 2;
            float b0v = bias[c], b1v = bias[c + 1];
            #pragma unroll
            for (int half = 0; half < 2; ++half) {
                int rr = r + half * 8;
                if (rr >= N) continue;
                float v0 = acc[mt][nt][2 * half + 0] + b0v;
                float v1 = acc[mt][nt][2 * half + 1] + b1v;
                if (do_relu) {
                    v0 = v0 > 0.f ? v0 : 0.f;
                    v1 = v1 > 0.f ? v1 : 0.f;
                }
                if (C) {
                    size_t o = (size_t)rr * M + c;
                    C[o] = v0;
                    C[o + 1] = v1;
                }
                if (C16) {
                    size_t o = (size_t)rr * M + c;
                    *(__half2*)(C16 + o) = __floats2half2_rn(v0, v1);
                }
                if (Chi) {
                    size_t o = ((size_t)blockIdx.y * nchC + (c >> 5)) * TILE_E
                             + (rr & 127) * 40 + (c & 31);
                    __nv_bfloat162 hh = __floats2bfloat162_rn(v0, v1);
                    __nv_bfloat162 ll = __floats2bfloat162_rn(
                        v0 - __bfloat162float(hh.x), v1 - __bfloat162float(hh.y));
                    *(unsigned*)(Chi + o) = *(unsigned*)&hh;
                    *(unsigned*)(Clo + o) = *(unsigned*)&ll;
                }
            }
        }
    }
}

// ---------------------------------------------------------------------------
// LayerNorm(128) + ReLU + pooling.  Warp per row group; no block syncs.
// ---------------------------------------------------------------------------
#define LNW 32

__global__ __launch_bounds__(256)
void ln_pool(const float* __restrict__ z, const float* __restrict__ lng,
             const float* __restrict__ lnb, const int* __restrict__ batch,
             float* __restrict__ xa, float* __restrict__ pooled, int N) {
    int warp = (blockIdx.x * blockDim.x + threadIdx.x) >> 5;
    int lane = threadIdx.x & 31;
    int r0 = warp * LNW;
    if (r0 >= N) return;
    int r1 = min(r0 + LNW, N);

    float4 g = ((const float4*)lng)[lane];
    float4 b = ((const float4*)lnb)[lane];

    float4 pacc = make_float4(0.f, 0.f, 0.f, 0.f);
    int curg = -1;
    for (int r = r0; r < r1; ++r) {
        float4 v = ((const float4*)(z + (size_t)r * 128))[lane];
        float s = v.x + v.y + v.z + v.w;
        float s2 = v.x * v.x + v.y * v.y + v.z * v.z + v.w * v.w;
        #pragma unroll
        for (int o = 16; o > 0; o >>= 1) {
            s  += __shfl_xor_sync(0xffffffffu, s, o);
            s2 += __shfl_xor_sync(0xffffffffu, s2, o);
        }
        float mu = s * (1.f / 128.f);
        float var = s2 * (1.f / 128.f) - mu * mu;
        float inv = rsqrtf(var + 1e-5f);
        float4 zz;
        zz.x = fmaxf((v.x - mu) * inv * g.x + b.x, 0.f);
        zz.y = fmaxf((v.y - mu) * inv * g.y + b.y, 0.f);
        zz.z = fmaxf((v.z - mu) * inv * g.z + b.z, 0.f);
        zz.w = fmaxf((v.w - mu) * inv * g.w + b.w, 0.f);
        ((float4*)(xa + (size_t)r * 128))[lane] = zz;

        int gb = batch[r];
        if (gb != curg) {
            if (curg >= 0) {
                float* pd = pooled + (size_t)curg * 128 + lane * 4;
                atomicAdd(pd + 0, pacc.x);
                atomicAdd(pd + 1, pacc.y);
                atomicAdd(pd + 2, pacc.z);
                atomicAdd(pd + 3, pacc.w);
            }
            curg = gb;
            pacc = make_float4(0.f, 0.f, 0.f, 0.f);
        }
        pacc.x += zz.x; pacc.y += zz.y; pacc.z += zz.z; pacc.w += zz.w;
    }
    if (curg >= 0) {
        float* pd = pooled + (size_t)curg * 128 + lane * 4;
        atomicAdd(pd + 0, pacc.x);
        atomicAdd(pd + 1, pacc.y);
        atomicAdd(pd + 2, pacc.z);
        atomicAdd(pd + 3, pacc.w);
    }
}

// ---------------------------------------------------------------------------
// Launch (prep chain + pooled zero overlapped on a second stream)
// ---------------------------------------------------------------------------
extern "C" void kernel_launch(void* const* d_in, const int* in_sizes, int n_in,
                              void* d_out, int out_size) {
    const float* x     = (const float*)d_in[0];
    const int*   ei    = (const int*)d_in[1];
    const int*   batch = (const int*)d_in[2];
    const float* W1r = (const float*)d_in[3];
    const float* b1  = (const float*)d_in[4];
    const float* W1o = (const float*)d_in[5];
    const float* W2r = (const float*)d_in[6];
    const float* b2  = (const float*)d_in[7];
    const float* W2o = (const float*)d_in[8];
    const float* W3r = (const float*)d_in[9];
    const float* b3  = (const float*)d_in[10];
    const float* W3o = (const float*)d_in[11];
    const float* Wfc = (const float*)d_in[12];
    const float* bfc = (const float*)d_in[13];
    const float* lng = (const float*)d_in[14];
    const float* lnb = (const float*)d_in[15];

    float* out = (float*)d_out;
    float* x_atom = out;
    float* pooled = out + (size_t)N_NODES * 128;

    float* zbuf;
    __half *h16, *x16;
    __nv_bfloat16 *aggh, *aggl, *bAh, *bAl, *bBh, *bBl, *wth, *wtl;
    cudaGetSymbolAddress((void**)&zbuf, g_z);
    cudaGetSymbolAddress((void**)&h16, g_h16);
    cudaGetSymbolAddress((void**)&x16, g_x16);
    cudaGetSymbolAddress((void**)&aggh, g_agg_hi);
    cudaGetSymbolAddress((void**)&aggl, g_agg_lo);
    cudaGetSymbolAddress((void**)&bAh, g_bufA_hi);
    cudaGetSymbolAddress((void**)&bAl, g_bufA_lo);
    cudaGetSymbolAddress((void**)&bBh, g_bufB_hi);
    cudaGetSymbolAddress((void**)&bBl, g_bufB_lo);
    cudaGetSymbolAddress((void**)&wth, g_wt_hi);
    cudaGetSymbolAddress((void**)&wtl, g_wt_lo);

    cudaFuncSetAttribute(dual_gemm_bf16,
                         cudaFuncAttributeMaxDynamicSharedMemorySize, 81920);

    static cudaStream_t sB = nullptr;
    static cudaEvent_t evFork = nullptr, evJoin = nullptr, evJoin2 = nullptr;
    if (sB == nullptr) {
        cudaStreamCreateWithFlags(&sB, cudaStreamNonBlocking);
        cudaEventCreateWithFlags(&evFork, cudaEventDisableTiming);
        cudaEventCreateWithFlags(&evJoin, cudaEventDisableTiming);
        cudaEventCreateWithFlags(&evJoin2, cudaEventDisableTiming);
    }

    const int gridY = NBLK;
    const int gatherBlocks = (N_NODES * 32 + 255) / 256;

    // ---- fork: weight/x prep on sB (join gates gather78);
    //      pooled zero afterwards on sB (join2 gates only ln_pool) ----
    cudaEventRecord(evFork, 0);
    cudaStreamWaitEvent(sB, evFork, 0);
    {
        PrepArgs pa;
        pa.W[0] = W1r; pa.K[0] = 78;  pa.M[0] = 256; pa.Kpad[0] = 96;  pa.off[0] = 0;
        pa.W[1] = W1o; pa.K[1] = 78;  pa.M[1] = 256; pa.Kpad[1] = 96;  pa.off[1] = 30720;
        pa.W[2] = W2r; pa.K[2] = 256; pa.M[2] = 512; pa.Kpad[2] = 256; pa.off[2] = 61440;
        pa.W[3] = W2o; pa.K[3] = 256; pa.M[3] = 512; pa.Kpad[3] = 256; pa.off[3] = 225280;
        pa.W[4] = W3r; pa.K[4] = 512; pa.M[4] = 512; pa.Kpad[4] = 512; pa.off[4] = 389120;
        pa.W[5] = W3o; pa.K[5] = 512; pa.M[5] = 512; pa.Kpad[5] = 512; pa.off[5] = 716800;
        pa.W[6] = Wfc; pa.K[6] = 512; pa.M[6] = 128; pa.Kpad[6] = 512; pa.off[6] = 1044480;
        dim3 grid((512 * 512 + 255) / 256, 7);
        prep_all<<<grid, 256, 0, sB>>>(pa, wth, wtl);
    }
    prep_x<<<(N_NODES * 96 + 255) / 256, 256, 0, sB>>>(x, bAh, bAl, x16);
    cudaEventRecord(evJoin, sB);
    zero_kernel<<<128, 256, 0, sB>>>((float4*)pooled, N_GRAPHS * 128 / 4);
    cudaEventRecord(evJoin2, sB);

    // main stream: CSR build
    {
        int* pcnt; cudaGetSymbolAddress((void**)&pcnt, g_cnt);
        zero_int<<<(N_NODES + 255) / 256, 256>>>(pcnt, N_NODES);
    }
    hist_kernel<<<(N_EDGES + 255) / 256, 256>>>(ei);
    scan1<<<(N_NODES + 1023) / 1024, 1024>>>();
    scan3<<<(N_NODES + 255) / 256, 256>>>();
    fill_kernel<<<(N_EDGES + 255) / 256, 256>>>(ei);

    // join before layer-1 gather (needs x16 from prep_x)
    cudaStreamWaitEvent(0, evJoin, 0);
    gather78<<<gatherBlocks, 256>>>(x16, aggh, aggl);

    // ---- Layer 1: 78 -> 256 (out: fp16 h + tiled bf16 hi/lo) ----
    {
        dim3 grid(2, gridY);
        dual_gemm_bf16<<<grid, 256, 81920>>>(aggh, aggl, bAh, bAl,
                                             wth + 0, wtl + 0,
                                             wth + 30720, wtl + 30720,
                                             b1, (float*)nullptr, h16, bBh, bBl,
                                             N_NODES, 96, 256, 1);
    }

    // ---- Layer 2: 256 -> 512 ----
    gather_h16<<<gatherBlocks, 256>>>(h16, 256, aggh, aggl);
    {
        dim3 grid(4, gridY);
        dual_gemm_bf16<<<grid, 256, 81920>>>(aggh, aggl, bBh, bBl,
                                             wth + 61440, wtl + 61440,
                                             wth + 225280, wtl + 225280,
                                             b2, (float*)nullptr, h16, bAh, bAl,
                                             N_NODES, 256, 512, 1);
    }

    // ---- Layer 3: 512 -> 512 ----
    gather_h16<<<gatherBlocks, 256>>>(h16, 512, aggh, aggl);
    {
        dim3 grid(4, gridY);
        dual_gemm_bf16<<<grid, 256, 81920>>>(aggh, aggl, bAh, bAl,
                                             wth + 389120, wtl + 389120,
                                             wth + 716800, wtl + 716800,
                                             b3, (float*)nullptr, (__half*)nullptr,
                                             bBh, bBl,
                                             N_NODES, 512, 512, 1);
    }

    // ---- FC 512->128 via GEMM (no relu), then LN + ReLU + pool ----
    {
        dim3 grid(1, gridY);
        dual_gemm_bf16<<<grid, 256, 81920>>>(bBh, bBl,
                                             (__nv_bfloat16*)nullptr,
                                             (__nv_bfloat16*)nullptr,
                                             wth + 1044480, wtl + 1044480,
                                             (__nv_bfloat16*)nullptr,
                                             (__nv_bfloat16*)nullptr,
                                             bfc, zbuf, (__half*)nullptr,
                                             (__nv_bfloat16*)nullptr,
                                             (__nv_bfloat16*)nullptr,
                                             N_NODES, 512, 128, 0);
    }
    cudaStreamWaitEvent(0, evJoin2, 0);
    {
        int warps = (N_NODES + LNW - 1) / LNW;
        ln_pool<<<(warps * 32 + 255) / 256, 256>>>(
            zbuf, lng, lnb, batch, x_atom, pooled, N_NODES);
    }
}

// round 16
// speedup vs baseline: 1.2643x; 1.1689x over previous
#include <cuda_runtime.h>
#include <cuda_bf16.h>
#include <cuda_fp16.h>
#include <cstdint>

#define N_NODES 50000
#define N_EDGES 800000
#define N_GRAPHS 1024
#define NBLK 391                 // ceil(50000/128)
#define TILE_E 5120              // elems per 10240B tile (128 rows x 40 fp16)
#define FEAT_E ((size_t)NBLK * 16 * TILE_E)

// ---------------- device-global scratch (allocation-free rule) -------------
__device__ float g_z[(size_t)N_NODES * 128];      // FC output
__device__ __half g_h16[(size_t)N_NODES * 512];   // fp16 inter-layer features
__device__ __half g_x16[(size_t)N_NODES * 78];    // fp16 copy of x
// tiled fp16 hi/lo feature buffers: [block][chunk][128x40]
__device__ __half g_agg_hi[FEAT_E];
__device__ __half g_agg_lo[FEAT_E];
__device__ __half g_bufA_hi[FEAT_E];
__device__ __half g_bufA_lo[FEAT_E];
__device__ __half g_bufB_hi[FEAT_E];
__device__ __half g_bufB_lo[FEAT_E];
// tiled weights (plain fp16), offsets in elems:
// W1r:0 W1o:30720 W2r:61440 W2o:225280 W3r:389120 W3o:716800 Wfc:1044480
__device__ __half g_wt16[1126400];
// CSR
__device__ int g_cnt[N_NODES];
__device__ int g_off[N_NODES + 1];
__device__ int g_cur[N_NODES];
__device__ int g_srcs[N_EDGES];
__device__ int g_bsum[64];

// ---------------------------------------------------------------------------
__global__ void zero_kernel(float4* __restrict__ p, int n4) {
    int i = blockIdx.x * blockDim.x + threadIdx.x;
    int stride = gridDim.x * blockDim.x;
    float4 z = make_float4(0.f, 0.f, 0.f, 0.f);
    for (; i < n4; i += stride) p[i] = z;
}

__global__ void zero_int(int* __restrict__ p, int n) {
    int i = blockIdx.x * blockDim.x + threadIdx.x;
    if (i < n) p[i] = 0;
}

// ---------------------------------------------------------------------------
// Fused weight prep: W [K,M] fp32 -> tiled [colblock][chunk][128x40] fp16
// ---------------------------------------------------------------------------
struct PrepArgs {
    const float* W[7];
    int K[7];
    int M[7];
    int Kpad[7];
    int off[7];
};

__global__ void prep_all(PrepArgs a, __half* __restrict__ w16) {
    int seg = blockIdx.y;
    int idx = blockIdx.x * blockDim.x + threadIdx.x;
    int Kpad = a.Kpad[seg];
    if (idx >= a.M[seg] * Kpad) return;
    int n = idx / Kpad, k = idx % Kpad;
    int K = a.K[seg];
    int nch = Kpad >> 5;
    float v = (k < K) ? a.W[seg][(size_t)k * a.M[seg] + n] : 0.f;
    size_t o = (size_t)a.off[seg]
             + ((size_t)(n >> 7) * nch + (k >> 5)) * TILE_E
             + (n & 127) * 40 + (k & 31);
    w16[o] = __float2half(v);
}

// x [N,78] fp32 -> tiled fp16 hi/lo (Kpad 96) + fp16 row-major copy
__global__ void prep_x(const float* __restrict__ x,
                       __half* __restrict__ hi,
                       __half* __restrict__ lo,
                       __half* __restrict__ x16) {
    int idx = blockIdx.x * blockDim.x + threadIdx.x;
    if (idx >= N_NODES * 96) return;
    int n = idx / 96, k = idx % 96;
    float v = (k < 78) ? x[(size_t)n * 78 + k] : 0.f;
    __half h = __float2half(v);
    size_t o = ((size_t)(n >> 7) * 3 + (k >> 5)) * TILE_E
             + (n & 127) * 40 + (k & 31);
    hi[o] = h;
    lo[o] = __float2half(v - __half2float(h));
    if (k < 78) x16[(size_t)n * 78 + k] = h;
}

// ---------------------------------------------------------------------------
// CSR build
// ---------------------------------------------------------------------------
__global__ void hist_kernel(const int* __restrict__ ei) {
    int e = blockIdx.x * blockDim.x + threadIdx.x;
    if (e < N_EDGES) atomicAdd(&g_cnt[ei[N_EDGES + e]], 1);
}

__global__ void scan1(void) {
    __shared__ int sm[1024];
    int tid = threadIdx.x;
    int i = blockIdx.x * 1024 + tid;
    int v = (i < N_NODES) ? g_cnt[i] : 0;
    sm[tid] = v;
    __syncthreads();
    for (int o = 1; o < 1024; o <<= 1) {
        int t = (tid >= o) ? sm[tid - o] : 0;
        __syncthreads();
        sm[tid] += t;
        __syncthreads();
    }
    if (i < N_NODES) g_off[i] = sm[tid] - v;
    if (tid == 1023) g_bsum[blockIdx.x] = sm[1023];
}

__global__ void scan3(void) {
    int i = blockIdx.x * blockDim.x + threadIdx.x;
    if (i < N_NODES) {
        int blk = i >> 10;
        int run = 0;
        for (int b = 0; b < blk; ++b) run += g_bsum[b];
        int o = g_off[i] + run;
        g_off[i] = o;
        g_cur[i] = o;
    }
    if (i == 0) g_off[N_NODES] = N_EDGES;
}

__global__ void fill_kernel(const int* __restrict__ ei) {
    int e = blockIdx.x * blockDim.x + threadIdx.x;
    if (e >= N_EDGES) return;
    int s = ei[e], t = ei[N_EDGES + e];
    int pos = atomicAdd(&g_cur[t], 1);
    g_srcs[pos] = s;
}

// ---------------------------------------------------------------------------
// CSR gather from fp16 x copy (layer 1) -> tiled fp16 hi/lo.  Warp per node.
// ---------------------------------------------------------------------------
__global__ void gather78(const __half* __restrict__ x,
                         __half* __restrict__ ahi,
                         __half* __restrict__ alo) {
    int n = (blockIdx.x * blockDim.x + threadIdx.x) >> 5;
    int lane = threadIdx.x & 31;
    if (n >= N_NODES) return;
    int jb = g_off[n], je = g_off[n + 1];
    float a0 = 0.f, a1 = 0.f, a2 = 0.f;
    for (int j = jb; j < je; ++j) {
        const __half* xr = x + (size_t)g_srcs[j] * 78;
        a0 += __half2float(__ldg(xr + lane));
        a1 += __half2float(__ldg(xr + lane + 32));
        if (lane < 14) a2 += __half2float(__ldg(xr + lane + 64));
    }
    float vals[3] = {a0, a1, (lane < 14) ? a2 : 0.f};
    size_t tbase = (size_t)(n >> 7) * 3;
    int rr = (n & 127) * 40 + lane;
    #pragma unroll
    for (int i = 0; i < 3; ++i) {
        size_t o = (tbase + i) * TILE_E + rr;
        __half h = __float2half(vals[i]);
        ahi[o] = h;
        alo[o] = __float2half(vals[i] - __half2float(h));
    }
}

// CSR gather from fp16 features (layers 2,3) -> tiled fp16 hi/lo.
__global__ void gather_h16(const __half* __restrict__ x, int d,
                           __half* __restrict__ ahi,
                           __half* __restrict__ alo) {
    int n = (blockIdx.x * blockDim.x + threadIdx.x) >> 5;
    int lane = threadIdx.x & 31;
    if (n >= N_NODES) return;
    int jb = g_off[n], je = g_off[n + 1];
    int ng = d >> 8;                    // 256-elem groups (1 or 2)
    float acc[16];
    #pragma unroll
    for (int i = 0; i < 16; ++i) acc[i] = 0.f;
    for (int j = jb; j < je; ++j) {
        const __half* xr = x + (size_t)g_srcs[j] * d;
        #pragma unroll 2
        for (int g = 0; g < ng; ++g) {
            uint4 v = __ldg((const uint4*)(xr + g * 256) + lane);
            const __half2* hp = (const __half2*)&v;
            #pragma unroll
            for (int p = 0; p < 4; ++p) {
                float2 f = __half22float2(hp[p]);
                acc[g * 8 + p * 2]     += f.x;
                acc[g * 8 + p * 2 + 1] += f.y;
            }
        }
    }
    size_t tb = (size_t)(n >> 7) * (d >> 5);
    int rbase = (n & 127) * 40;
    for (int g = 0; g < ng; ++g) {
        int c0 = g * 256 + lane * 8;
        int ch = c0 >> 5;
        int co = c0 & 31;
        #pragma unroll
        for (int hf = 0; hf < 2; ++hf) {
            float a0 = acc[g * 8 + hf * 4 + 0];
            float a1 = acc[g * 8 + hf * 4 + 1];
            float a2 = acc[g * 8 + hf * 4 + 2];
            float a3 = acc[g * 8 + hf * 4 + 3];
            __half2 h01 = __floats2half2_rn(a0, a1);
            __half2 h23 = __floats2half2_rn(a2, a3);
            float2 f01 = __half22float2(h01);
            float2 f23 = __half22float2(h23);
            __half2 l01 = __floats2half2_rn(a0 - f01.x, a1 - f01.y);
            __half2 l23 = __floats2half2_rn(a2 - f23.x, a3 - f23.y);
            size_t o = (tb + ch) * TILE_E + rbase + co + hf * 4;
            *(uint2*)(ahi + o) = make_uint2(*(unsigned*)&h01, *(unsigned*)&h23);
            *(uint2*)(alo + o) = make_uint2(*(unsigned*)&l01, *(unsigned*)&l23);
        }
    }
}

// ---------------------------------------------------------------------------
// mma / ldmatrix / bulk-copy helpers
// ---------------------------------------------------------------------------
__device__ __forceinline__ void mma_f16(float* c, const unsigned* a,
                                        unsigned b0, unsigned b1) {
    asm volatile(
        "mma.sync.aligned.m16n8k16.row.col.f32.f16.f16.f32 "
        "{%0,%1,%2,%3}, {%4,%5,%6,%7}, {%8,%9}, {%0,%1,%2,%3};"
        : "+f"(c[0]), "+f"(c[1]), "+f"(c[2]), "+f"(c[3])
        : "r"(a[0]), "r"(a[1]), "r"(a[2]), "r"(a[3]), "r"(b0), "r"(b1));
}

__device__ __forceinline__ void ldm_x4(unsigned* r, uint32_t addr) {
    asm volatile(
        "ldmatrix.sync.aligned.m8n8.x4.shared.b16 {%0,%1,%2,%3}, [%4];"
        : "=r"(r[0]), "=r"(r[1]), "=r"(r[2]), "=r"(r[3]) : "r"(addr));
}

__device__ __forceinline__ void ldm_x2(unsigned* r, uint32_t addr) {
    asm volatile(
        "ldmatrix.sync.aligned.m8n8.x2.shared.b16 {%0,%1}, [%2];"
        : "=r"(r[0]), "=r"(r[1]) : "r"(addr));
}

__device__ __forceinline__ void bulkcp(uint32_t dst, const void* src,
                                       uint32_t mbar) {
    asm volatile(
        "cp.async.bulk.shared::cluster.global.mbarrier::complete_tx::bytes "
        "[%0], [%1], %2, [%3];"
        :: "r"(dst), "l"(src), "r"(10240u), "r"(mbar) : "memory");
}

__device__ __forceinline__ void mbar_wait(uint32_t addr, uint32_t phase) {
    asm volatile(
        "{\n\t.reg .pred p;\n\t"
        "WL%=:\n\t"
        "mbarrier.try_wait.parity.acquire.cta.shared::cta.b64 p, [%0], %1, 0x989680;\n\t"
        "@p bra WD%=;\n\t"
        "bra WL%=;\n\t"
        "WD%=:\n\t}"
        :: "r"(addr), "r"(phase) : "memory");
}

// ---------------------------------------------------------------------------
// Dual/single GEMM, fp16 2-term split: D = a_hi.W + a_lo.W, W plain fp16.
//   C = act(A1 @ W1 [+ A2 @ W2] + bias)
// 3 bulk copies / iter (Ah, Al, W).  Warp grid 4x2 (proven shape; frozen).
// ---------------------------------------------------------------------------
#define TILE_B 10240
#define STAGE_B 30720

__global__ __launch_bounds__(256, 2)
void dual_gemm_f16(const __half* __restrict__ A1h,
                   const __half* __restrict__ A1l,
                   const __half* __restrict__ A2h,
                   const __half* __restrict__ A2l,
                   const __half* __restrict__ W1,
                   const __half* __restrict__ W2,
                   const float* __restrict__ bias, float* __restrict__ C,
                   __half* __restrict__ C16,
                   __half* __restrict__ Chi,
                   __half* __restrict__ Clo,
                   int N, int Kpad, int M, int do_relu) {
    extern __shared__ __align__(16) char dynsmem[];
    __shared__ __align__(8) uint64_t s_mbar[2];
    uint32_t ubase = (uint32_t)__cvta_generic_to_shared(dynsmem);
    uint32_t mbase = (uint32_t)__cvta_generic_to_shared(s_mbar);

    int tid = threadIdx.x;
    int lane = tid & 31, wid = tid >> 5;
    int wr = wid & 3, wc = wid >> 2;
    int m0w = wr * 32, n0w = wc * 64;
    int gid = lane >> 2, tig = lane & 3;

    int rowBase = blockIdx.y * 128;
    int colBase = blockIdx.x * 128;

    int a_row = (lane & 7) + ((lane >> 3) & 1) * 8;
    int a_koff = (lane >> 4) * 16;
    int b_row = lane & 7;
    int b_koff = ((lane >> 3) & 1) * 16;

    if (tid == 0) {
        asm volatile("mbarrier.init.shared.b64 [%0], 1;" :: "r"(mbase) : "memory");
        asm volatile("mbarrier.init.shared.b64 [%0], 1;" :: "r"(mbase + 8) : "memory");
    }
    __syncthreads();

    float acc[2][8][4];
    #pragma unroll
    for (int mt = 0; mt < 2; mt++)
        #pragma unroll
        for (int nt = 0; nt < 8; nt++)
            #pragma unroll
            for (int i = 0; i < 4; i++) acc[mt][nt][i] = 0.f;

    const int nch = Kpad >> 5;
    const int npass = (A2h != nullptr) ? 2 : 1;
    const int T = npass * nch;

    auto issue = [&](int it, int st) {
        if (tid == 0) {
            int pass = (it >= nch) ? 1 : 0;
            int ch = it - pass * nch;
            const __half* AH = pass ? A2h : A1h;
            const __half* AL = pass ? A2l : A1l;
            const __half* WW = pass ? W2 : W1;
            uint32_t mb = mbase + st * 8;
            asm volatile("mbarrier.arrive.expect_tx.shared.b64 _, [%0], %1;"
                         :: "r"(mb), "r"(30720u) : "memory");
            uint32_t sb = ubase + st * STAGE_B;
            size_t at = ((size_t)blockIdx.y * nch + ch) * TILE_E;
            size_t bt = ((size_t)blockIdx.x * nch + ch) * TILE_E;
            bulkcp(sb,              AH + at, mb);
            bulkcp(sb + TILE_B,     AL + at, mb);
            bulkcp(sb + 2 * TILE_B, WW + bt, mb);
        }
    };

    int ph0 = 0, ph1 = 0;
    issue(0, 0);

    #pragma unroll 1
    for (int it = 0; it < T; ++it) {
        if (it + 1 < T) issue(it + 1, (it + 1) & 1);
        int st = it & 1;
        mbar_wait(mbase + st * 8, st ? ph1 : ph0);
        if (st) ph1 ^= 1; else ph0 ^= 1;

        uint32_t sb = ubase + st * STAGE_B;
        uint32_t uAh = sb, uAl = sb + TILE_B;
        uint32_t uW = sb + 2 * TILE_B;

        #pragma unroll
        for (int ks = 0; ks < 2; ++ks) {
            int kb = ks * 32;
            unsigned ah[2][4], al[2][4];
            #pragma unroll
            for (int mt = 0; mt < 2; mt++) {
                uint32_t ao = (uint32_t)((m0w + mt * 16 + a_row) * 80
                                         + kb + a_koff);
                ldm_x4(ah[mt], uAh + ao);
                ldm_x4(al[mt], uAl + ao);
            }
            #pragma unroll
            for (int nt = 0; nt < 8; nt++) {
                uint32_t bo = (uint32_t)((n0w + nt * 8 + b_row) * 80
                                         + kb + b_koff);
                unsigned bw[2];
                ldm_x2(bw, uW + bo);
                #pragma unroll
                for (int mt = 0; mt < 2; mt++) {
                    mma_f16(acc[mt][nt], ah[mt], bw[0], bw[1]);
                    mma_f16(acc[mt][nt], al[mt], bw[0], bw[1]);
                }
            }
        }
        __syncthreads();   // all reads done before next bulk overwrites stage
    }

    // ---- Epilogue ----
    const int nchC = M >> 5;
    #pragma unroll
    for (int mt = 0; mt < 2; mt++) {
        #pragma unroll
        for (int nt = 0; nt < 8; nt++) {
            int r = rowBase + m0w + mt * 16 + gid;
            int c = colBase + n0w + nt * 8 + tig * 2;
            float b0v = bias[c], b1v = bias[c + 1];
            #pragma unroll
            for (int half = 0; half < 2; ++half) {
                int rr = r + half * 8;
                if (rr >= N) continue;
                float v0 = acc[mt][nt][2 * half + 0] + b0v;
                float v1 = acc[mt][nt][2 * half + 1] + b1v;
                if (do_relu) {
                    v0 = v0 > 0.f ? v0 : 0.f;
                    v1 = v1 > 0.f ? v1 : 0.f;
                }
                if (C) {
                    size_t o = (size_t)rr * M + c;
                    C[o] = v0;
                    C[o + 1] = v1;
                }
                if (C16) {
                    size_t o = (size_t)rr * M + c;
                    *(__half2*)(C16 + o) = __floats2half2_rn(v0, v1);
                }
                if (Chi) {
                    size_t o = ((size_t)blockIdx.y * nchC + (c >> 5)) * TILE_E
                             + (rr & 127) * 40 + (c & 31);
                    __half2 hh = __floats2half2_rn(v0, v1);
                    float2 fh = __half22float2(hh);
                    __half2 ll = __floats2half2_rn(v0 - fh.x, v1 - fh.y);
                    *(unsigned*)(Chi + o) = *(unsigned*)&hh;
                    *(unsigned*)(Clo + o) = *(unsigned*)&ll;
                }
            }
        }
    }
}

// ---------------------------------------------------------------------------
// LayerNorm(128) + ReLU + pooling.  Warp per row group; no block syncs.
// ---------------------------------------------------------------------------
#define LNW 32

__global__ __launch_bounds__(256)
void ln_pool(const float* __restrict__ z, const float* __restrict__ lng,
             const float* __restrict__ lnb, const int* __restrict__ batch,
             float* __restrict__ xa, float* __restrict__ pooled, int N) {
    int warp = (blockIdx.x * blockDim.x + threadIdx.x) >> 5;
    int lane = threadIdx.x & 31;
    int r0 = warp * LNW;
    if (r0 >= N) return;
    int r1 = min(r0 + LNW, N);

    float4 g = ((const float4*)lng)[lane];
    float4 b = ((const float4*)lnb)[lane];

    float4 pacc = make_float4(0.f, 0.f, 0.f, 0.f);
    int curg = -1;
    for (int r = r0; r < r1; ++r) {
        float4 v = ((const float4*)(z + (size_t)r * 128))[lane];
        float s = v.x + v.y + v.z + v.w;
        float s2 = v.x * v.x + v.y * v.y + v.z * v.z + v.w * v.w;
        #pragma unroll
        for (int o = 16; o > 0; o >>= 1) {
            s  += __shfl_xor_sync(0xffffffffu, s, o);
            s2 += __shfl_xor_sync(0xffffffffu, s2, o);
        }
        float mu = s * (1.f / 128.f);
        float var = s2 * (1.f / 128.f) - mu * mu;
        float inv = rsqrtf(var + 1e-5f);
        float4 zz;
        zz.x = fmaxf((v.x - mu) * inv * g.x + b.x, 0.f);
        zz.y = fmaxf((v.y - mu) * inv * g.y + b.y, 0.f);
        zz.z = fmaxf((v.z - mu) * inv * g.z + b.z, 0.f);
        zz.w = fmaxf((v.w - mu) * inv * g.w + b.w, 0.f);
        ((float4*)(xa + (size_t)r * 128))[lane] = zz;

        int gb = batch[r];
        if (gb != curg) {
            if (curg >= 0) {
                float* pd = pooled + (size_t)curg * 128 + lane * 4;
                atomicAdd(pd + 0, pacc.x);
                atomicAdd(pd + 1, pacc.y);
                atomicAdd(pd + 2, pacc.z);
                atomicAdd(pd + 3, pacc.w);
            }
            curg = gb;
            pacc = make_float4(0.f, 0.f, 0.f, 0.f);
        }
        pacc.x += zz.x; pacc.y += zz.y; pacc.z += zz.z; pacc.w += zz.w;
    }
    if (curg >= 0) {
        float* pd = pooled + (size_t)curg * 128 + lane * 4;
        atomicAdd(pd + 0, pacc.x);
        atomicAdd(pd + 1, pacc.y);
        atomicAdd(pd + 2, pacc.z);
        atomicAdd(pd + 3, pacc.w);
    }
}

// ---------------------------------------------------------------------------
// Launch (prep chain + pooled zero overlapped on a second stream)
// ---------------------------------------------------------------------------
extern "C" void kernel_launch(void* const* d_in, const int* in_sizes, int n_in,
                              void* d_out, int out_size) {
    const float* x     = (const float*)d_in[0];
    const int*   ei    = (const int*)d_in[1];
    const int*   batch = (const int*)d_in[2];
    const float* W1r = (const float*)d_in[3];
    const float* b1  = (const float*)d_in[4];
    const float* W1o = (const float*)d_in[5];
    const float* W2r = (const float*)d_in[6];
    const float* b2  = (const float*)d_in[7];
    const float* W2o = (const float*)d_in[8];
    const float* W3r = (const float*)d_in[9];
    const float* b3  = (const float*)d_in[10];
    const float* W3o = (const float*)d_in[11];
    const float* Wfc = (const float*)d_in[12];
    const float* bfc = (const float*)d_in[13];
    const float* lng = (const float*)d_in[14];
    const float* lnb = (const float*)d_in[15];

    float* out = (float*)d_out;
    float* x_atom = out;
    float* pooled = out + (size_t)N_NODES * 128;

    float* zbuf;
    __half *h16, *x16, *aggh, *aggl, *bAh, *bAl, *bBh, *bBl, *wt16;
    cudaGetSymbolAddress((void**)&zbuf, g_z);
    cudaGetSymbolAddress((void**)&h16, g_h16);
    cudaGetSymbolAddress((void**)&x16, g_x16);
    cudaGetSymbolAddress((void**)&aggh, g_agg_hi);
    cudaGetSymbolAddress((void**)&aggl, g_agg_lo);
    cudaGetSymbolAddress((void**)&bAh, g_bufA_hi);
    cudaGetSymbolAddress((void**)&bAl, g_bufA_lo);
    cudaGetSymbolAddress((void**)&bBh, g_bufB_hi);
    cudaGetSymbolAddress((void**)&bBl, g_bufB_lo);
    cudaGetSymbolAddress((void**)&wt16, g_wt16);

    cudaFuncSetAttribute(dual_gemm_f16,
                         cudaFuncAttributeMaxDynamicSharedMemorySize, 61440);

    static cudaStream_t sB = nullptr;
    static cudaEvent_t evFork = nullptr, evJoin = nullptr, evJoin2 = nullptr;
    if (sB == nullptr) {
        cudaStreamCreateWithFlags(&sB, cudaStreamNonBlocking);
        cudaEventCreateWithFlags(&evFork, cudaEventDisableTiming);
        cudaEventCreateWithFlags(&evJoin, cudaEventDisableTiming);
        cudaEventCreateWithFlags(&evJoin2, cudaEventDisableTiming);
    }

    const int gridY = NBLK;
    const int gatherBlocks = (N_NODES * 32 + 255) / 256;

    // ---- fork: weight/x prep on sB; pooled zero after (gates only ln_pool) ----
    cudaEventRecord(evFork, 0);
    cudaStreamWaitEvent(sB, evFork, 0);
    {
        PrepArgs pa;
        pa.W[0] = W1r; pa.K[0] = 78;  pa.M[0] = 256; pa.Kpad[0] = 96;  pa.off[0] = 0;
        pa.W[1] = W1o; pa.K[1] = 78;  pa.M[1] = 256; pa.Kpad[1] = 96;  pa.off[1] = 30720;
        pa.W[2] = W2r; pa.K[2] = 256; pa.M[2] = 512; pa.Kpad[2] = 256; pa.off[2] = 61440;
        pa.W[3] = W2o; pa.K[3] = 256; pa.M[3] = 512; pa.Kpad[3] = 256; pa.off[3] = 225280;
        pa.W[4] = W3r; pa.K[4] = 512; pa.M[4] = 512; pa.Kpad[4] = 512; pa.off[4] = 389120;
        pa.W[5] = W3o; pa.K[5] = 512; pa.M[5] = 512; pa.Kpad[5] = 512; pa.off[5] = 716800;
        pa.W[6] = Wfc; pa.K[6] = 512; pa.M[6] = 128; pa.Kpad[6] = 512; pa.off[6] = 1044480;
        dim3 grid((512 * 512 + 255) / 256, 7);
        prep_all<<<grid, 256, 0, sB>>>(pa, wt16);
    }
    prep_x<<<(N_NODES * 96 + 255) / 256, 256, 0, sB>>>(x, bAh, bAl, x16);
    cudaEventRecord(evJoin, sB);
    zero_kernel<<<128, 256, 0, sB>>>((float4*)pooled, N_GRAPHS * 128 / 4);
    cudaEventRecord(evJoin2, sB);

    // main stream: CSR build
    {
        int* pcnt; cudaGetSymbolAddress((void**)&pcnt, g_cnt);
        zero_int<<<(N_NODES + 255) / 256, 256>>>(pcnt, N_NODES);
    }
    hist_kernel<<<(N_EDGES + 255) / 256, 256>>>(ei);
    scan1<<<(N_NODES + 1023) / 1024, 1024>>>();
    scan3<<<(N_NODES + 255) / 256, 256>>>();
    fill_kernel<<<(N_EDGES + 255) / 256, 256>>>(ei);

    // join before layer-1 gather (needs x16 from prep_x)
    cudaStreamWaitEvent(0, evJoin, 0);
    gather78<<<gatherBlocks, 256>>>(x16, aggh, aggl);

    // ---- Layer 1: 78 -> 256 (out: fp16 row-major + tiled fp16 hi/lo) ----
    {
        dim3 grid(2, gridY);
        dual_gemm_f16<<<grid, 256, 61440>>>(aggh, aggl, bAh, bAl,
                                            wt16 + 0, wt16 + 30720,
                                            b1, (float*)nullptr, h16, bBh, bBl,
                                            N_NODES, 96, 256, 1);
    }

    // ---- Layer 2: 256 -> 512 ----
    gather_h16<<<gatherBlocks, 256>>>(h16, 256, aggh, aggl);
    {
        dim3 grid(4, gridY);
        dual_gemm_f16<<<grid, 256, 61440>>>(aggh, aggl, bBh, bBl,
                                            wt16 + 61440, wt16 + 225280,
                                            b2, (float*)nullptr, h16, bAh, bAl,
                                            N_NODES, 256, 512, 1);
    }

    // ---- Layer 3: 512 -> 512 ----
    gather_h16<<<gatherBlocks, 256>>>(h16, 512, aggh, aggl);
    {
        dim3 grid(4, gridY);
        dual_gemm_f16<<<grid, 256, 61440>>>(aggh, aggl, bAh, bAl,
                                            wt16 + 389120, wt16 + 716800,
                                            b3, (float*)nullptr, (__half*)nullptr,
                                            bBh, bBl,
                                            N_NODES, 512, 512, 1);
    }

    // ---- FC 512->128 via GEMM (no relu), then LN + ReLU + pool ----
    {
        dim3 grid(1, gridY);
        dual_gemm_f16<<<grid, 256, 61440>>>(bBh, bBl,
                                            (__half*)nullptr, (__half*)nullptr,
                                            wt16 + 1044480, (__half*)nullptr,
                                            bfc, zbuf, (__half*)nullptr,
                                            (__half*)nullptr, (__half*)nullptr,
                                            N_NODES, 512, 128, 0);
    }
    cudaStreamWaitEvent(0, evJoin2, 0);
    {
        int warps = (N_NODES + LNW - 1) / LNW;
        ln_pool<<<(warps * 32 + 255) / 256, 256>>>(
            zbuf, lng, lnb, batch, x_atom, pooled, N_NODES);
    }
}

// round 17
// speedup vs baseline: 1.2971x; 1.0260x over previous
#include <cuda_runtime.h>
#include <cuda_bf16.h>
#include <cuda_fp16.h>
#include <cstdint>

#define N_NODES 50000
#define N_EDGES 800000
#define N_GRAPHS 1024
#define NBLK 391                 // ceil(50000/128)
#define TILE_E 5120              // elems per 10240B tile (128 rows x 40 fp16)
#define FEAT_E ((size_t)NBLK * 16 * TILE_E)

// ---------------- device-global scratch (allocation-free rule) -------------
__device__ float g_z[(size_t)N_NODES * 128];      // FC output
__device__ __half g_h16[(size_t)N_NODES * 512];   // fp16 inter-layer features
__device__ __half g_x16[(size_t)N_NODES * 78];    // fp16 copy of x
// tiled fp16 hi/lo feature buffers: [block][chunk][128x40]
__device__ __half g_agg_hi[FEAT_E];
__device__ __half g_agg_lo[FEAT_E];
__device__ __half g_bufA_hi[FEAT_E];
__device__ __half g_bufA_lo[FEAT_E];
__device__ __half g_bufB_hi[FEAT_E];
__device__ __half g_bufB_lo[FEAT_E];
// tiled weights (plain fp16), offsets in elems:
// W1r:0 W1o:30720 W2r:61440 W2o:225280 W3r:389120 W3o:716800 Wfc:1044480
__device__ __half g_wt16[1126400];
// CSR
__device__ int g_cnt[N_NODES];
__device__ int g_off[N_NODES + 1];
__device__ int g_cur[N_NODES];
__device__ int g_srcs[N_EDGES];
__device__ int g_bsum[64];

// ---------------------------------------------------------------------------
__global__ void zero_kernel(float4* __restrict__ p, int n4) {
    int i = blockIdx.x * blockDim.x + threadIdx.x;
    int stride = gridDim.x * blockDim.x;
    float4 z = make_float4(0.f, 0.f, 0.f, 0.f);
    for (; i < n4; i += stride) p[i] = z;
}

__global__ void zero_int(int* __restrict__ p, int n) {
    int i = blockIdx.x * blockDim.x + threadIdx.x;
    if (i < n) p[i] = 0;
}

// ---------------------------------------------------------------------------
// Fused weight prep: W [K,M] fp32 -> tiled [colblock][chunk][128x40] fp16
// ---------------------------------------------------------------------------
struct PrepArgs {
    const float* W[7];
    int K[7];
    int M[7];
    int Kpad[7];
    int off[7];
};

__global__ void prep_all(PrepArgs a, __half* __restrict__ w16) {
    int seg = blockIdx.y;
    int idx = blockIdx.x * blockDim.x + threadIdx.x;
    int Kpad = a.Kpad[seg];
    if (idx >= a.M[seg] * Kpad) return;
    int n = idx / Kpad, k = idx % Kpad;
    int K = a.K[seg];
    int nch = Kpad >> 5;
    float v = (k < K) ? a.W[seg][(size_t)k * a.M[seg] + n] : 0.f;
    size_t o = (size_t)a.off[seg]
             + ((size_t)(n >> 7) * nch + (k >> 5)) * TILE_E
             + (n & 127) * 40 + (k & 31);
    w16[o] = __float2half(v);
}

// x [N,78] fp32 -> tiled fp16 hi/lo (Kpad 96) + fp16 row-major copy
__global__ void prep_x(const float* __restrict__ x,
                       __half* __restrict__ hi,
                       __half* __restrict__ lo,
                       __half* __restrict__ x16) {
    int idx = blockIdx.x * blockDim.x + threadIdx.x;
    if (idx >= N_NODES * 96) return;
    int n = idx / 96, k = idx % 96;
    float v = (k < 78) ? x[(size_t)n * 78 + k] : 0.f;
    __half h = __float2half(v);
    size_t o = ((size_t)(n >> 7) * 3 + (k >> 5)) * TILE_E
             + (n & 127) * 40 + (k & 31);
    hi[o] = h;
    lo[o] = __float2half(v - __half2float(h));
    if (k < 78) x16[(size_t)n * 78 + k] = h;
}

// ---------------------------------------------------------------------------
// CSR build
// ---------------------------------------------------------------------------
__global__ void hist_kernel(const int* __restrict__ ei) {
    int e = blockIdx.x * blockDim.x + threadIdx.x;
    if (e < N_EDGES) atomicAdd(&g_cnt[ei[N_EDGES + e]], 1);
}

__global__ void scan1(void) {
    __shared__ int sm[1024];
    int tid = threadIdx.x;
    int i = blockIdx.x * 1024 + tid;
    int v = (i < N_NODES) ? g_cnt[i] : 0;
    sm[tid] = v;
    __syncthreads();
    for (int o = 1; o < 1024; o <<= 1) {
        int t = (tid >= o) ? sm[tid - o] : 0;
        __syncthreads();
        sm[tid] += t;
        __syncthreads();
    }
    if (i < N_NODES) g_off[i] = sm[tid] - v;
    if (tid == 1023) g_bsum[blockIdx.x] = sm[1023];
}

__global__ void scan3(void) {
    int i = blockIdx.x * blockDim.x + threadIdx.x;
    if (i < N_NODES) {
        int blk = i >> 10;
        int run = 0;
        for (int b = 0; b < blk; ++b) run += g_bsum[b];
        int o = g_off[i] + run;
        g_off[i] = o;
        g_cur[i] = o;
    }
    if (i == 0) g_off[N_NODES] = N_EDGES;
}

__global__ void fill_kernel(const int* __restrict__ ei) {
    int e = blockIdx.x * blockDim.x + threadIdx.x;
    if (e >= N_EDGES) return;
    int s = ei[e], t = ei[N_EDGES + e];
    int pos = atomicAdd(&g_cur[t], 1);
    g_srcs[pos] = s;
}

// ---------------------------------------------------------------------------
// CSR gather from fp16 x copy (layer 1) -> tiled fp16 hi/lo.  Warp per node.
// ---------------------------------------------------------------------------
__global__ void gather78(const __half* __restrict__ x,
                         __half* __restrict__ ahi,
                         __half* __restrict__ alo) {
    int n = (blockIdx.x * blockDim.x + threadIdx.x) >> 5;
    int lane = threadIdx.x & 31;
    if (n >= N_NODES) return;
    int jb = g_off[n], je = g_off[n + 1];
    float a0 = 0.f, a1 = 0.f, a2 = 0.f;
    for (int j = jb; j < je; ++j) {
        const __half* xr = x + (size_t)g_srcs[j] * 78;
        a0 += __half2float(__ldg(xr + lane));
        a1 += __half2float(__ldg(xr + lane + 32));
        if (lane < 14) a2 += __half2float(__ldg(xr + lane + 64));
    }
    float vals[3] = {a0, a1, (lane < 14) ? a2 : 0.f};
    size_t tbase = (size_t)(n >> 7) * 3;
    int rr = (n & 127) * 40 + lane;
    #pragma unroll
    for (int i = 0; i < 3; ++i) {
        size_t o = (tbase + i) * TILE_E + rr;
        __half h = __float2half(vals[i]);
        ahi[o] = h;
        alo[o] = __float2half(vals[i] - __half2float(h));
    }
}

// CSR gather from fp16 features (layers 2,3) -> tiled fp16 hi/lo.
__global__ void gather_h16(const __half* __restrict__ x, int d,
                           __half* __restrict__ ahi,
                           __half* __restrict__ alo) {
    int n = (blockIdx.x * blockDim.x + threadIdx.x) >> 5;
    int lane = threadIdx.x & 31;
    if (n >= N_NODES) return;
    int jb = g_off[n], je = g_off[n + 1];
    int ng = d >> 8;                    // 256-elem groups (1 or 2)
    float acc[16];
    #pragma unroll
    for (int i = 0; i < 16; ++i) acc[i] = 0.f;
    for (int j = jb; j < je; ++j) {
        const __half* xr = x + (size_t)g_srcs[j] * d;
        #pragma unroll 2
        for (int g = 0; g < ng; ++g) {
            uint4 v = __ldg((const uint4*)(xr + g * 256) + lane);
            const __half2* hp = (const __half2*)&v;
            #pragma unroll
            for (int p = 0; p < 4; ++p) {
                float2 f = __half22float2(hp[p]);
                acc[g * 8 + p * 2]     += f.x;
                acc[g * 8 + p * 2 + 1] += f.y;
            }
        }
    }
    size_t tb = (size_t)(n >> 7) * (d >> 5);
    int rbase = (n & 127) * 40;
    for (int g = 0; g < ng; ++g) {
        int c0 = g * 256 + lane * 8;
        int ch = c0 >> 5;
        int co = c0 & 31;
        #pragma unroll
        for (int hf = 0; hf < 2; ++hf) {
            float a0 = acc[g * 8 + hf * 4 + 0];
            float a1 = acc[g * 8 + hf * 4 + 1];
            float a2 = acc[g * 8 + hf * 4 + 2];
            float a3 = acc[g * 8 + hf * 4 + 3];
            __half2 h01 = __floats2half2_rn(a0, a1);
            __half2 h23 = __floats2half2_rn(a2, a3);
            float2 f01 = __half22float2(h01);
            float2 f23 = __half22float2(h23);
            __half2 l01 = __floats2half2_rn(a0 - f01.x, a1 - f01.y);
            __half2 l23 = __floats2half2_rn(a2 - f23.x, a3 - f23.y);
            size_t o = (tb + ch) * TILE_E + rbase + co + hf * 4;
            *(uint2*)(ahi + o) = make_uint2(*(unsigned*)&h01, *(unsigned*)&h23);
            *(uint2*)(alo + o) = make_uint2(*(unsigned*)&l01, *(unsigned*)&l23);
        }
    }
}

// ---------------------------------------------------------------------------
// mma / ldmatrix / bulk-copy helpers
// ---------------------------------------------------------------------------
__device__ __forceinline__ void mma_f16(float* c, const unsigned* a,
                                        unsigned b0, unsigned b1) {
    asm volatile(
        "mma.sync.aligned.m16n8k16.row.col.f32.f16.f16.f32 "
        "{%0,%1,%2,%3}, {%4,%5,%6,%7}, {%8,%9}, {%0,%1,%2,%3};"
        : "+f"(c[0]), "+f"(c[1]), "+f"(c[2]), "+f"(c[3])
        : "r"(a[0]), "r"(a[1]), "r"(a[2]), "r"(a[3]), "r"(b0), "r"(b1));
}

__device__ __forceinline__ void ldm_x4(unsigned* r, uint32_t addr) {
    asm volatile(
        "ldmatrix.sync.aligned.m8n8.x4.shared.b16 {%0,%1,%2,%3}, [%4];"
        : "=r"(r[0]), "=r"(r[1]), "=r"(r[2]), "=r"(r[3]) : "r"(addr));
}

__device__ __forceinline__ void ldm_x2(unsigned* r, uint32_t addr) {
    asm volatile(
        "ldmatrix.sync.aligned.m8n8.x2.shared.b16 {%0,%1}, [%2];"
        : "=r"(r[0]), "=r"(r[1]) : "r"(addr));
}

__device__ __forceinline__ void bulkcp(uint32_t dst, const void* src,
                                       uint32_t mbar) {
    asm volatile(
        "cp.async.bulk.shared::cluster.global.mbarrier::complete_tx::bytes "
        "[%0], [%1], %2, [%3];"
        :: "r"(dst), "l"(src), "r"(10240u), "r"(mbar) : "memory");
}

__device__ __forceinline__ void mbar_wait(uint32_t addr, uint32_t phase) {
    asm volatile(
        "{\n\t.reg .pred p;\n\t"
        "WL%=:\n\t"
        "mbarrier.try_wait.parity.acquire.cta.shared::cta.b64 p, [%0], %1, 0x989680;\n\t"
        "@p bra WD%=;\n\t"
        "bra WL%=;\n\t"
        "WD%=:\n\t}"
        :: "r"(addr), "r"(phase) : "memory");
}

// ---------------------------------------------------------------------------
// Dual/single GEMM, fp16 2-term split: D = a_hi.W + a_lo.W, W plain fp16.
//   C = act(A1 @ W1 [+ A2 @ W2] + bias)
// 3-stage cp.async.bulk pipeline (prefetch depth 2) hides copy latency.
// Warp grid 4x2 (proven shape; frozen -- R8/R14 regressions on reshapes).
// ---------------------------------------------------------------------------
#define TILE_B 10240
#define STAGE_B 30720
#define NSTAGE 3

__global__ __launch_bounds__(256, 2)
void dual_gemm_f16(const __half* __restrict__ A1h,
                   const __half* __restrict__ A1l,
                   const __half* __restrict__ A2h,
                   const __half* __restrict__ A2l,
                   const __half* __restrict__ W1,
                   const __half* __restrict__ W2,
                   const float* __restrict__ bias, float* __restrict__ C,
                   __half* __restrict__ C16,
                   __half* __restrict__ Chi,
                   __half* __restrict__ Clo,
                   int N, int Kpad, int M, int do_relu) {
    extern __shared__ __align__(16) char dynsmem[];
    __shared__ __align__(8) uint64_t s_mbar[NSTAGE];
    uint32_t ubase = (uint32_t)__cvta_generic_to_shared(dynsmem);
    uint32_t mbase = (uint32_t)__cvta_generic_to_shared(s_mbar);

    int tid = threadIdx.x;
    int lane = tid & 31, wid = tid >> 5;
    int wr = wid & 3, wc = wid >> 2;
    int m0w = wr * 32, n0w = wc * 64;
    int gid = lane >> 2, tig = lane & 3;

    int rowBase = blockIdx.y * 128;
    int colBase = blockIdx.x * 128;

    int a_row = (lane & 7) + ((lane >> 3) & 1) * 8;
    int a_koff = (lane >> 4) * 16;
    int b_row = lane & 7;
    int b_koff = ((lane >> 3) & 1) * 16;

    if (tid == 0) {
        #pragma unroll
        for (int s = 0; s < NSTAGE; ++s)
            asm volatile("mbarrier.init.shared.b64 [%0], 1;"
                         :: "r"(mbase + s * 8) : "memory");
    }
    __syncthreads();

    float acc[2][8][4];
    #pragma unroll
    for (int mt = 0; mt < 2; mt++)
        #pragma unroll
        for (int nt = 0; nt < 8; nt++)
            #pragma unroll
            for (int i = 0; i < 4; i++) acc[mt][nt][i] = 0.f;

    const int nch = Kpad >> 5;
    const int npass = (A2h != nullptr) ? 2 : 1;
    const int T = npass * nch;

    auto issue = [&](int it, int st) {
        if (tid == 0) {
            int pass = (it >= nch) ? 1 : 0;
            int ch = it - pass * nch;
            const __half* AH = pass ? A2h : A1h;
            const __half* AL = pass ? A2l : A1l;
            const __half* WW = pass ? W2 : W1;
            uint32_t mb = mbase + st * 8;
            asm volatile("mbarrier.arrive.expect_tx.shared.b64 _, [%0], %1;"
                         :: "r"(mb), "r"(30720u) : "memory");
            uint32_t sb = ubase + st * STAGE_B;
            size_t at = ((size_t)blockIdx.y * nch + ch) * TILE_E;
            size_t bt = ((size_t)blockIdx.x * nch + ch) * TILE_E;
            bulkcp(sb,              AH + at, mb);
            bulkcp(sb + TILE_B,     AL + at, mb);
            bulkcp(sb + 2 * TILE_B, WW + bt, mb);
        }
    };

    int ph[NSTAGE];
    #pragma unroll
    for (int s = 0; s < NSTAGE; ++s) ph[s] = 0;

    issue(0, 0);
    if (T > 1) issue(1, 1);

    int st = 0;
    #pragma unroll 1
    for (int it = 0; it < T; ++it) {
        if (it + 2 < T) {
            int st2 = st + 2;
            if (st2 >= NSTAGE) st2 -= NSTAGE;
            issue(it + 2, st2);
        }
        mbar_wait(mbase + st * 8, ph[st]);
        ph[st] ^= 1;

        uint32_t sb = ubase + st * STAGE_B;
        uint32_t uAh = sb, uAl = sb + TILE_B;
        uint32_t uW = sb + 2 * TILE_B;

        #pragma unroll
        for (int ks = 0; ks < 2; ++ks) {
            int kb = ks * 32;
            unsigned ah[2][4], al[2][4];
            #pragma unroll
            for (int mt = 0; mt < 2; mt++) {
                uint32_t ao = (uint32_t)((m0w + mt * 16 + a_row) * 80
                                         + kb + a_koff);
                ldm_x4(ah[mt], uAh + ao);
                ldm_x4(al[mt], uAl + ao);
            }
            #pragma unroll
            for (int nt = 0; nt < 8; nt++) {
                uint32_t bo = (uint32_t)((n0w + nt * 8 + b_row) * 80
                                         + kb + b_koff);
                unsigned bw[2];
                ldm_x2(bw, uW + bo);
                #pragma unroll
                for (int mt = 0; mt < 2; mt++) {
                    mma_f16(acc[mt][nt], ah[mt], bw[0], bw[1]);
                    mma_f16(acc[mt][nt], al[mt], bw[0], bw[1]);
                }
            }
        }
        __syncthreads();   // ordering chain: stage reuse is 3 iters away
        if (++st == NSTAGE) st = 0;
    }

    // ---- Epilogue ----
    const int nchC = M >> 5;
    #pragma unroll
    for (int mt = 0; mt < 2; mt++) {
        #pragma unroll
        for (int nt = 0; nt < 8; nt++) {
            int r = rowBase + m0w + mt * 16 + gid;
            int c = colBase + n0w + nt * 8 + tig * 2;
            float b0v = bias[c], b1v = bias[c + 1];
            #pragma unroll
            for (int half = 0; half < 2; ++half) {
                int rr = r + half * 8;
                if (rr >= N) continue;
                float v0 = acc[mt][nt][2 * half + 0] + b0v;
                float v1 = acc[mt][nt][2 * half + 1] + b1v;
                if (do_relu) {
                    v0 = v0 > 0.f ? v0 : 0.f;
                    v1 = v1 > 0.f ? v1 : 0.f;
                }
                if (C) {
                    size_t o = (size_t)rr * M + c;
                    C[o] = v0;
                    C[o + 1] = v1;
                }
                if (C16) {
                    size_t o = (size_t)rr * M + c;
                    *(__half2*)(C16 + o) = __floats2half2_rn(v0, v1);
                }
                if (Chi) {
                    size_t o = ((size_t)blockIdx.y * nchC + (c >> 5)) * TILE_E
                             + (rr & 127) * 40 + (c & 31);
                    __half2 hh = __floats2half2_rn(v0, v1);
                    float2 fh = __half22float2(hh);
                    __half2 ll = __floats2half2_rn(v0 - fh.x, v1 - fh.y);
                    *(unsigned*)(Chi + o) = *(unsigned*)&hh;
                    *(unsigned*)(Clo + o) = *(unsigned*)&ll;
                }
            }
        }
    }
}

// ---------------------------------------------------------------------------
// LayerNorm(128) + ReLU + pooling.  Warp per row group; no block syncs.
// ---------------------------------------------------------------------------
#define LNW 32

__global__ __launch_bounds__(256)
void ln_pool(const float* __restrict__ z, const float* __restrict__ lng,
             const float* __restrict__ lnb, const int* __restrict__ batch,
             float* __restrict__ xa, float* __restrict__ pooled, int N) {
    int warp = (blockIdx.x * blockDim.x + threadIdx.x) >> 5;
    int lane = threadIdx.x & 31;
    int r0 = warp * LNW;
    if (r0 >= N) return;
    int r1 = min(r0 + LNW, N);

    float4 g = ((const float4*)lng)[lane];
    float4 b = ((const float4*)lnb)[lane];

    float4 pacc = make_float4(0.f, 0.f, 0.f, 0.f);
    int curg = -1;
    for (int r = r0; r < r1; ++r) {
        float4 v = ((const float4*)(z + (size_t)r * 128))[lane];
        float s = v.x + v.y + v.z + v.w;
        float s2 = v.x * v.x + v.y * v.y + v.z * v.z + v.w * v.w;
        #pragma unroll
        for (int o = 16; o > 0; o >>= 1) {
            s  += __shfl_xor_sync(0xffffffffu, s, o);
            s2 += __shfl_xor_sync(0xffffffffu, s2, o);
        }
        float mu = s * (1.f / 128.f);
        float var = s2 * (1.f / 128.f) - mu * mu;
        float inv = rsqrtf(var + 1e-5f);
        float4 zz;
        zz.x = fmaxf((v.x - mu) * inv * g.x + b.x, 0.f);
        zz.y = fmaxf((v.y - mu) * inv * g.y + b.y, 0.f);
        zz.z = fmaxf((v.z - mu) * inv * g.z + b.z, 0.f);
        zz.w = fmaxf((v.w - mu) * inv * g.w + b.w, 0.f);
        ((float4*)(xa + (size_t)r * 128))[lane] = zz;

        int gb = batch[r];
        if (gb != curg) {
            if (curg >= 0) {
                float* pd = pooled + (size_t)curg * 128 + lane * 4;
                atomicAdd(pd + 0, pacc.x);
                atomicAdd(pd + 1, pacc.y);
                atomicAdd(pd + 2, pacc.z);
                atomicAdd(pd + 3, pacc.w);
            }
            curg = gb;
            pacc = make_float4(0.f, 0.f, 0.f, 0.f);
        }
        pacc.x += zz.x; pacc.y += zz.y; pacc.z += zz.z; pacc.w += zz.w;
    }
    if (curg >= 0) {
        float* pd = pooled + (size_t)curg * 128 + lane * 4;
        atomicAdd(pd + 0, pacc.x);
        atomicAdd(pd + 1, pacc.y);
        atomicAdd(pd + 2, pacc.z);
        atomicAdd(pd + 3, pacc.w);
    }
}

// ---------------------------------------------------------------------------
// Launch (prep chain + pooled zero overlapped on a second stream)
// ---------------------------------------------------------------------------
extern "C" void kernel_launch(void* const* d_in, const int* in_sizes, int n_in,
                              void* d_out, int out_size) {
    const float* x     = (const float*)d_in[0];
    const int*   ei    = (const int*)d_in[1];
    const int*   batch = (const int*)d_in[2];
    const float* W1r = (const float*)d_in[3];
    const float* b1  = (const float*)d_in[4];
    const float* W1o = (const float*)d_in[5];
    const float* W2r = (const float*)d_in[6];
    const float* b2  = (const float*)d_in[7];
    const float* W2o = (const float*)d_in[8];
    const float* W3r = (const float*)d_in[9];
    const float* b3  = (const float*)d_in[10];
    const float* W3o = (const float*)d_in[11];
    const float* Wfc = (const float*)d_in[12];
    const float* bfc = (const float*)d_in[13];
    const float* lng = (const float*)d_in[14];
    const float* lnb = (const float*)d_in[15];

    float* out = (float*)d_out;
    float* x_atom = out;
    float* pooled = out + (size_t)N_NODES * 128;

    float* zbuf;
    __half *h16, *x16, *aggh, *aggl, *bAh, *bAl, *bBh, *bBl, *wt16;
    cudaGetSymbolAddress((void**)&zbuf, g_z);
    cudaGetSymbolAddress((void**)&h16, g_h16);
    cudaGetSymbolAddress((void**)&x16, g_x16);
    cudaGetSymbolAddress((void**)&aggh, g_agg_hi);
    cudaGetSymbolAddress((void**)&aggl, g_agg_lo);
    cudaGetSymbolAddress((void**)&bAh, g_bufA_hi);
    cudaGetSymbolAddress((void**)&bAl, g_bufA_lo);
    cudaGetSymbolAddress((void**)&bBh, g_bufB_hi);
    cudaGetSymbolAddress((void**)&bBl, g_bufB_lo);
    cudaGetSymbolAddress((void**)&wt16, g_wt16);

    cudaFuncSetAttribute(dual_gemm_f16,
                         cudaFuncAttributeMaxDynamicSharedMemorySize, 92160);

    static cudaStream_t sB = nullptr;
    static cudaEvent_t evFork = nullptr, evJoin = nullptr, evJoin2 = nullptr;
    if (sB == nullptr) {
        cudaStreamCreateWithFlags(&sB, cudaStreamNonBlocking);
        cudaEventCreateWithFlags(&evFork, cudaEventDisableTiming);
        cudaEventCreateWithFlags(&evJoin, cudaEventDisableTiming);
        cudaEventCreateWithFlags(&evJoin2, cudaEventDisableTiming);
    }

    const int gridY = NBLK;
    const int gatherBlocks = (N_NODES * 32 + 255) / 256;

    // ---- fork: weight/x prep on sB; pooled zero after (gates only ln_pool) ----
    cudaEventRecord(evFork, 0);
    cudaStreamWaitEvent(sB, evFork, 0);
    {
        PrepArgs pa;
        pa.W[0] = W1r; pa.K[0] = 78;  pa.M[0] = 256; pa.Kpad[0] = 96;  pa.off[0] = 0;
        pa.W[1] = W1o; pa.K[1] = 78;  pa.M[1] = 256; pa.Kpad[1] = 96;  pa.off[1] = 30720;
        pa.W[2] = W2r; pa.K[2] = 256; pa.M[2] = 512; pa.Kpad[2] = 256; pa.off[2] = 61440;
        pa.W[3] = W2o; pa.K[3] = 256; pa.M[3] = 512; pa.Kpad[3] = 256; pa.off[3] = 225280;
        pa.W[4] = W3r; pa.K[4] = 512; pa.M[4] = 512; pa.Kpad[4] = 512; pa.off[4] = 389120;
        pa.W[5] = W3o; pa.K[5] = 512; pa.M[5] = 512; pa.Kpad[5] = 512; pa.off[5] = 716800;
        pa.W[6] = Wfc; pa.K[6] = 512; pa.M[6] = 128; pa.Kpad[6] = 512; pa.off[6] = 1044480;
        dim3 grid((512 * 512 + 255) / 256, 7);
        prep_all<<<grid, 256, 0, sB>>>(pa, wt16);
    }
    prep_x<<<(N_NODES * 96 + 255) / 256, 256, 0, sB>>>(x, bAh, bAl, x16);
    cudaEventRecord(evJoin, sB);
    zero_kernel<<<128, 256, 0, sB>>>((float4*)pooled, N_GRAPHS * 128 / 4);
    cudaEventRecord(evJoin2, sB);

    // main stream: CSR build
    {
        int* pcnt; cudaGetSymbolAddress((void**)&pcnt, g_cnt);
        zero_int<<<(N_NODES + 255) / 256, 256>>>(pcnt, N_NODES);
    }
    hist_kernel<<<(N_EDGES + 255) / 256, 256>>>(ei);
    scan1<<<(N_NODES + 1023) / 1024, 1024>>>();
    scan3<<<(N_NODES + 255) / 256, 256>>>();
    fill_kernel<<<(N_EDGES + 255) / 256, 256>>>(ei);

    // join before layer-1 gather (needs x16 from prep_x)
    cudaStreamWaitEvent(0, evJoin, 0);
    gather78<<<gatherBlocks, 256>>>(x16, aggh, aggl);

    // ---- Layer 1: 78 -> 256 (out: fp16 row-major + tiled fp16 hi/lo) ----
    {
        dim3 grid(2, gridY);
        dual_gemm_f16<<<grid, 256, 92160>>>(aggh, aggl, bAh, bAl,
                                            wt16 + 0, wt16 + 30720,
                                            b1, (float*)nullptr, h16, bBh, bBl,
                                            N_NODES, 96, 256, 1);
    }

    // ---- Layer 2: 256 -> 512 ----
    gather_h16<<<gatherBlocks, 256>>>(h16, 256, aggh, aggl);
    {
        dim3 grid(4, gridY);
        dual_gemm_f16<<<grid, 256, 92160>>>(aggh, aggl, bBh, bBl,
                                            wt16 + 61440, wt16 + 225280,
                                            b2, (float*)nullptr, h16, bAh, bAl,
                                            N_NODES, 256, 512, 1);
    }

    // ---- Layer 3: 512 -> 512 ----
    gather_h16<<<gatherBlocks, 256>>>(h16, 512, aggh, aggl);
    {
        dim3 grid(4, gridY);
        dual_gemm_f16<<<grid, 256, 92160>>>(aggh, aggl, bAh, bAl,
                                            wt16 + 389120, wt16 + 716800,
                                            b3, (float*)nullptr, (__half*)nullptr,
                                            bBh, bBl,
                                            N_NODES, 512, 512, 1);
    }

    // ---- FC 512->128 via GEMM (no relu), then LN + ReLU + pool ----
    {
        dim3 grid(1, gridY);
        dual_gemm_f16<<<grid, 256, 92160>>>(bBh, bBl,
                                            (__half*)nullptr, (__half*)nullptr,
                                            wt16 + 1044480, (__half*)nullptr,
                                            bfc, zbuf, (__half*)nullptr,
                                            (__half*)nullptr, (__half*)nullptr,
                                            N_NODES, 512, 128, 0);
    }
    cudaStreamWaitEvent(0, evJoin2, 0);
    {
        int warps = (N_NODES + LNW - 1) / LNW;
        ln_pool<<<(warps * 32 + 255) / 256, 256>>>(
            zbuf, lng, lnb, batch, x_atom, pooled, N_NODES);
    }
}